// round 1
// baseline (speedup 1.0000x reference)
#include <cuda_runtime.h>
#include <math.h>
#include <stdint.h>

#define B_BATCH 4096
#define H_DIM   1024
#define IN_DIM  10338
#define OUT_DIM 229
#define BN_EPS  1e-5f

// ---------------- scratch (device globals; no allocation allowed) ----------
__device__ float g_A [(size_t)B_BATCH * H_DIM];   // pre-BN GEMM output
__device__ float g_H0[(size_t)B_BATCH * H_DIM];
__device__ float g_H1[(size_t)B_BATCH * H_DIM];
__device__ float g_O4[(size_t)B_BATCH * OUT_DIM];
__device__ float g_scale[H_DIM];
__device__ float g_shift[H_DIM];

// ---------------- tiled fp32 GEMM: C[M,N] = A[M,K] @ W[K,N] + bias ---------
#define BM 128
#define BN 128
#define BK 16
#define TM 8
#define TN 8

__global__ void __launch_bounds__(256)
gemm_bias_kernel(const float* __restrict__ A, const float* __restrict__ W,
                 const float* __restrict__ bias, float* __restrict__ C,
                 int M, int N, int K)
{
    __shared__ float As[BK][BM];
    __shared__ float Ws[BK][BN];

    const int tid = threadIdx.x;
    const int m0  = blockIdx.y * BM;
    const int n0  = blockIdx.x * BN;
    const int tm  = (tid / 16) * TM;
    const int tn  = (tid % 16) * TN;

    float acc[TM][TN];
#pragma unroll
    for (int i = 0; i < TM; i++)
#pragma unroll
        for (int j = 0; j < TN; j++) acc[i][j] = 0.f;

    for (int k0 = 0; k0 < K; k0 += BK) {
        // A tile: BM x BK = 2048 elems, 8 per thread
#pragma unroll
        for (int i = 0; i < 8; i++) {
            int idx = i * 256 + tid;
            int r   = idx / BK;
            int kk  = idx % BK;
            int gm  = m0 + r, gk = k0 + kk;
            As[kk][r] = (gm < M && gk < K) ? A[(size_t)gm * K + gk] : 0.f;
        }
        // W tile: BK x BN = 2048 elems
#pragma unroll
        for (int i = 0; i < 8; i++) {
            int idx = i * 256 + tid;
            int kk  = idx / BN;
            int c   = idx % BN;
            int gk  = k0 + kk, gn = n0 + c;
            Ws[kk][c] = (gk < K && gn < N) ? W[(size_t)gk * N + gn] : 0.f;
        }
        __syncthreads();

#pragma unroll
        for (int kk = 0; kk < BK; kk++) {
            float ra[TM], rb[TN];
            const float4* a4 = reinterpret_cast<const float4*>(&As[kk][tm]);
            float4 av0 = a4[0], av1 = a4[1];
            ra[0]=av0.x; ra[1]=av0.y; ra[2]=av0.z; ra[3]=av0.w;
            ra[4]=av1.x; ra[5]=av1.y; ra[6]=av1.z; ra[7]=av1.w;
            const float4* b4 = reinterpret_cast<const float4*>(&Ws[kk][tn]);
            float4 bv0 = b4[0], bv1 = b4[1];
            rb[0]=bv0.x; rb[1]=bv0.y; rb[2]=bv0.z; rb[3]=bv0.w;
            rb[4]=bv1.x; rb[5]=bv1.y; rb[6]=bv1.z; rb[7]=bv1.w;
#pragma unroll
            for (int i = 0; i < TM; i++)
#pragma unroll
                for (int j = 0; j < TN; j++)
                    acc[i][j] = fmaf(ra[i], rb[j], acc[i][j]);
        }
        __syncthreads();
    }

#pragma unroll
    for (int i = 0; i < TM; i++) {
        int gm = m0 + tm + i;
        if (gm >= M) continue;
#pragma unroll
        for (int j = 0; j < TN; j++) {
            int gn = n0 + tn + j;
            if (gn < N) C[(size_t)gm * N + gn] = acc[i][j] + bias[gn];
        }
    }
}

// --------------- batchnorm stats -> fused scale/shift per column ----------
// grid: N/32 blocks, block 256 = 32 cols x 8 row-groups
__global__ void bn_stats_kernel(const float* __restrict__ X,
                                const float* __restrict__ gamma,
                                const float* __restrict__ beta,
                                float* __restrict__ scale,
                                float* __restrict__ shift,
                                int M, int N)
{
    int lane = threadIdx.x % 32;
    int ry   = threadIdx.x / 32;           // 0..7
    int col  = blockIdx.x * 32 + lane;

    float s = 0.f, q = 0.f;
    for (int r = ry; r < M; r += 8) {
        float v = X[(size_t)r * N + col];
        s += v;
        q += v * v;
    }
    __shared__ float ss[8][33], sq[8][33];
    ss[ry][lane] = s;
    sq[ry][lane] = q;
    __syncthreads();
    if (ry == 0) {
#pragma unroll
        for (int i = 1; i < 8; i++) { s += ss[i][lane]; q += sq[i][lane]; }
        float inv = 1.f / (float)M;
        float mu  = s * inv;
        float var = q * inv - mu * mu;
        float rs  = rsqrtf(var + BN_EPS);
        float sc  = gamma[col] * rs;
        scale[col] = sc;
        shift[col] = beta[col] - mu * sc;
    }
}

// --------------- BN apply (+optional residual) + relu, float4 -------------
__global__ void bn_apply_kernel(const float* __restrict__ X,
                                const float* __restrict__ scale,
                                const float* __restrict__ shift,
                                const float* __restrict__ res,   // may be null
                                float* __restrict__ Y,
                                int total4, int N)
{
    int i = blockIdx.x * blockDim.x + threadIdx.x;
    if (i >= total4) return;
    int c0 = (i * 4) & (N - 1);           // N is power of two (1024)
    float4 x = reinterpret_cast<const float4*>(X)[i];
    float4 o;
    o.x = x.x * scale[c0 + 0] + shift[c0 + 0];
    o.y = x.y * scale[c0 + 1] + shift[c0 + 1];
    o.z = x.z * scale[c0 + 2] + shift[c0 + 2];
    o.w = x.w * scale[c0 + 3] + shift[c0 + 3];
    if (res) {
        float4 h = reinterpret_cast<const float4*>(res)[i];
        o.x += h.x; o.y += h.y; o.z += h.z; o.w += h.w;
    }
    o.x = fmaxf(o.x, 0.f); o.y = fmaxf(o.y, 0.f);
    o.z = fmaxf(o.z, 0.f); o.w = fmaxf(o.w, 0.f);
    reinterpret_cast<float4*>(Y)[i] = o;
}

// --------------- polar factor of 3x3 (replaces SVD U@Vh) ------------------
// Determinant-scaled Newton: X <- 0.5*(g*X + sign(d)*g^2*cof(X)), g=|d|^(-1/3)
__global__ void polar_kernel(const float* __restrict__ O,
                             float* __restrict__ out, int B)
{
    int i = blockIdx.x * blockDim.x + threadIdx.x;
    if (i >= B * 24) return;
    int b = i / 24, j = i % 24;
    const float* m = O + (size_t)b * OUT_DIM + j * 9;

    float X[9];
#pragma unroll
    for (int k = 0; k < 9; k++) X[k] = m[k];

#pragma unroll
    for (int it = 0; it < 14; it++) {
        float C0 = X[4]*X[8] - X[5]*X[7];
        float C1 = X[5]*X[6] - X[3]*X[8];
        float C2 = X[3]*X[7] - X[4]*X[6];
        float C3 = X[2]*X[7] - X[1]*X[8];
        float C4 = X[0]*X[8] - X[2]*X[6];
        float C5 = X[1]*X[6] - X[0]*X[7];
        float C6 = X[1]*X[5] - X[2]*X[4];
        float C7 = X[2]*X[3] - X[0]*X[5];
        float C8 = X[0]*X[4] - X[1]*X[3];
        float d  = X[0]*C0 + X[1]*C1 + X[2]*C2;
        float ad = fmaxf(fabsf(d), 1e-30f);
        float g  = 1.f / cbrtf(ad);          // |d|^(-1/3)
        float c2 = copysignf(g * g, d);      // sign(d)*|d|^(-2/3)
        X[0] = 0.5f*(g*X[0] + c2*C0);
        X[1] = 0.5f*(g*X[1] + c2*C1);
        X[2] = 0.5f*(g*X[2] + c2*C2);
        X[3] = 0.5f*(g*X[3] + c2*C3);
        X[4] = 0.5f*(g*X[4] + c2*C4);
        X[5] = 0.5f*(g*X[5] + c2*C5);
        X[6] = 0.5f*(g*X[6] + c2*C6);
        X[7] = 0.5f*(g*X[7] + c2*C7);
        X[8] = 0.5f*(g*X[8] + c2*C8);
    }
    // det sign correction: R *= det(R) (det is +-1 for orthogonal R)
    float det = X[0]*(X[4]*X[8]-X[5]*X[7])
              - X[1]*(X[3]*X[8]-X[5]*X[6])
              + X[2]*(X[3]*X[7]-X[4]*X[6]);
    float s = (det >= 0.f) ? 1.f : -1.f;
    float* dst = out + (size_t)i * 9;
#pragma unroll
    for (int k = 0; k < 9; k++) dst[k] = X[k] * s;
}

// --------------- betas + camera tail copy ----------------------------------
__global__ void tail_kernel(const float* __restrict__ O,
                            float* __restrict__ out, int B)
{
    int i = blockIdx.x * blockDim.x + threadIdx.x;
    if (i >= B * 13) return;
    int b = i / 13, t = i % 13;
    size_t betas_off  = (size_t)B * 216;
    size_t camera_off = betas_off + (size_t)B * 10;
    if (t < 10)
        out[betas_off + (size_t)b * 10 + t] = O[(size_t)b * OUT_DIM + 216 + t];
    else
        out[camera_off + (size_t)b * 3 + (t - 10)] = O[(size_t)b * OUT_DIM + 226 + (t - 10)];
}

// ---------------------------------------------------------------------------
static void launch_gemm(const float* A, const float* W, const float* bias,
                        float* C, int M, int N, int K)
{
    dim3 grid((N + BN - 1) / BN, (M + BM - 1) / BM);
    gemm_bias_kernel<<<grid, 256>>>(A, W, bias, C, M, N, K);
}

static void launch_bn(const float* X, const float* g, const float* be,
                      float* scale, float* shift,
                      const float* res, float* Y)
{
    bn_stats_kernel<<<H_DIM / 32, 256>>>(X, g, be, scale, shift, B_BATCH, H_DIM);
    int total4 = B_BATCH * H_DIM / 4;
    bn_apply_kernel<<<(total4 + 255) / 256, 256>>>(X, scale, shift, res, Y,
                                                   total4, H_DIM);
}

extern "C" void kernel_launch(void* const* d_in, const int* in_sizes, int n_in,
                              void* d_out, int out_size)
{
    const float* x    = (const float*)d_in[0];
    const float* w1   = (const float*)d_in[1];
    const float* b1   = (const float*)d_in[2];
    const float* g1   = (const float*)d_in[3];
    const float* be1  = (const float*)d_in[4];
    const float* w2a  = (const float*)d_in[5];
    const float* b2a  = (const float*)d_in[6];
    const float* g2a  = (const float*)d_in[7];
    const float* be2a = (const float*)d_in[8];
    const float* w2b  = (const float*)d_in[9];
    const float* b2b  = (const float*)d_in[10];
    const float* g2b  = (const float*)d_in[11];
    const float* be2b = (const float*)d_in[12];
    const float* w3a  = (const float*)d_in[13];
    const float* b3a  = (const float*)d_in[14];
    const float* g3a  = (const float*)d_in[15];
    const float* be3a = (const float*)d_in[16];
    const float* w3b  = (const float*)d_in[17];
    const float* b3b  = (const float*)d_in[18];
    const float* g3b  = (const float*)d_in[19];
    const float* be3b = (const float*)d_in[20];
    const float* w4   = (const float*)d_in[21];
    const float* b4   = (const float*)d_in[22];
    float* out = (float*)d_out;

    float *A, *H0, *H1, *O4, *sc, *sh;
    cudaGetSymbolAddress((void**)&A,  g_A);
    cudaGetSymbolAddress((void**)&H0, g_H0);
    cudaGetSymbolAddress((void**)&H1, g_H1);
    cudaGetSymbolAddress((void**)&O4, g_O4);
    cudaGetSymbolAddress((void**)&sc, g_scale);
    cudaGetSymbolAddress((void**)&sh, g_shift);

    // layer 1: h = relu(bn(x@w1 + b1))
    launch_gemm(x, w1, b1, A, B_BATCH, H_DIM, IN_DIM);
    launch_bn(A, g1, be1, sc, sh, nullptr, H0);          // H0 = h

    // resblock 2
    launch_gemm(H0, w2a, b2a, A, B_BATCH, H_DIM, H_DIM);
    launch_bn(A, g2a, be2a, sc, sh, nullptr, H1);        // H1 = t
    launch_gemm(H1, w2b, b2b, A, B_BATCH, H_DIM, H_DIM);
    launch_bn(A, g2b, be2b, sc, sh, H0, H1);             // H1 = relu(h + bn(..))

    // resblock 3
    launch_gemm(H1, w3a, b3a, A, B_BATCH, H_DIM, H_DIM);
    launch_bn(A, g3a, be3a, sc, sh, nullptr, H0);
    launch_gemm(H0, w3b, b3b, A, B_BATCH, H_DIM, H_DIM);
    launch_bn(A, g3b, be3b, sc, sh, H1, H0);             // H0 = final h

    // output head
    launch_gemm(H0, w4, b4, O4, B_BATCH, OUT_DIM, H_DIM);

    // polar decomposition (SVD replacement) + tail copies
    int nmat = B_BATCH * 24;
    polar_kernel<<<(nmat + 127) / 128, 128>>>(O4, out, B_BATCH);
    int ntail = B_BATCH * 13;
    tail_kernel<<<(ntail + 255) / 256, 256>>>(O4, out, B_BATCH);
}

// round 5
// speedup vs baseline: 1.3003x; 1.3003x over previous
#include <cuda_runtime.h>
#include <cuda_bf16.h>
#include <math.h>
#include <stdint.h>

#define B_BATCH 4096
#define H_DIM   1024
#define IN_DIM  10338
#define IN_PAD  10368
#define OUT_DIM 229
#define BN_EPS  1e-5f

// ---------------- MMA GEMM tiling -------------------------------------------
#define BM 128
#define BNT 64
#define BK 32
#define SMS 40                              // smem row stride (bf16), 80B
#define A_CB (BM * SMS * 2)                 // 10240 bytes per class
#define B_CB (BNT * SMS * 2)                // 5120 bytes per class
#define OFF_AH 0
#define OFF_AM (A_CB)
#define OFF_AL (2 * A_CB)
#define OFF_BH (3 * A_CB)
#define OFF_BM (3 * A_CB + B_CB)
#define OFF_BL (3 * A_CB + 2 * B_CB)
#define STAGE_BYTES (3 * A_CB + 3 * B_CB)   // 46080
#define SMEM_REQ (2 * STAGE_BYTES)          // 92160

// ---------------- scratch (device globals; no allocation allowed) ----------
__device__ float g_A [(size_t)B_BATCH * H_DIM];
__device__ float g_H0[(size_t)B_BATCH * H_DIM];
__device__ float g_H1[(size_t)B_BATCH * H_DIM];
__device__ float g_O4[(size_t)B_BATCH * OUT_DIM];
__device__ float g_scale[H_DIM];
__device__ float g_shift[H_DIM];

__device__ __nv_bfloat16 g_Xh[(size_t)B_BATCH * IN_PAD];
__device__ __nv_bfloat16 g_Xm[(size_t)B_BATCH * IN_PAD];
__device__ __nv_bfloat16 g_Xl[(size_t)B_BATCH * IN_PAD];
__device__ __nv_bfloat16 g_Ah[(size_t)B_BATCH * H_DIM];
__device__ __nv_bfloat16 g_Am[(size_t)B_BATCH * H_DIM];
__device__ __nv_bfloat16 g_Al[(size_t)B_BATCH * H_DIM];

__device__ __nv_bfloat16 g_W1h[(size_t)H_DIM * IN_PAD];
__device__ __nv_bfloat16 g_W1m[(size_t)H_DIM * IN_PAD];
__device__ __nv_bfloat16 g_W1l[(size_t)H_DIM * IN_PAD];
__device__ __nv_bfloat16 g_W2ah[(size_t)H_DIM * H_DIM];
__device__ __nv_bfloat16 g_W2am[(size_t)H_DIM * H_DIM];
__device__ __nv_bfloat16 g_W2al[(size_t)H_DIM * H_DIM];
__device__ __nv_bfloat16 g_W2bh[(size_t)H_DIM * H_DIM];
__device__ __nv_bfloat16 g_W2bm[(size_t)H_DIM * H_DIM];
__device__ __nv_bfloat16 g_W2bl[(size_t)H_DIM * H_DIM];
__device__ __nv_bfloat16 g_W3ah[(size_t)H_DIM * H_DIM];
__device__ __nv_bfloat16 g_W3am[(size_t)H_DIM * H_DIM];
__device__ __nv_bfloat16 g_W3al[(size_t)H_DIM * H_DIM];
__device__ __nv_bfloat16 g_W3bh[(size_t)H_DIM * H_DIM];
__device__ __nv_bfloat16 g_W3bm[(size_t)H_DIM * H_DIM];
__device__ __nv_bfloat16 g_W3bl[(size_t)H_DIM * H_DIM];

// ---------------- PTX helpers (baseline PTX; no sm_103a features) ----------
__device__ __forceinline__ uint32_t smem_u32(const void* p) {
    uint32_t a;
    asm("{ .reg .u64 t; cvta.to.shared.u64 t, %1; cvt.u32.u64 %0, t; }"
        : "=r"(a) : "l"(p));
    return a;
}
__device__ __forceinline__ void cp16(uint32_t dst, const void* src) {
    asm volatile("cp.async.cg.shared.global [%0], [%1], 16;" :: "r"(dst), "l"(src));
}
__device__ __forceinline__ void cp_commit() { asm volatile("cp.async.commit_group;" ::: "memory"); }
__device__ __forceinline__ void cp_wait1()  { asm volatile("cp.async.wait_group 1;" ::: "memory"); }
__device__ __forceinline__ void cp_wait0()  { asm volatile("cp.async.wait_group 0;" ::: "memory"); }

__device__ __forceinline__ void ldsm4(uint32_t r[4], uint32_t addr) {
    asm volatile("ldmatrix.sync.aligned.m8n8.x4.shared.b16 {%0,%1,%2,%3}, [%4];"
                 : "=r"(r[0]), "=r"(r[1]), "=r"(r[2]), "=r"(r[3]) : "r"(addr));
}
__device__ __forceinline__ void mma_bf16(float c[4], const uint32_t a[4],
                                         const uint32_t b[2]) {
    asm volatile(
        "mma.sync.aligned.m16n8k16.row.col.f32.bf16.bf16.f32 "
        "{%0,%1,%2,%3}, {%4,%5,%6,%7}, {%8,%9}, {%0,%1,%2,%3};"
        : "+f"(c[0]), "+f"(c[1]), "+f"(c[2]), "+f"(c[3])
        : "r"(a[0]), "r"(a[1]), "r"(a[2]), "r"(a[3]), "r"(b[0]), "r"(b[1]));
}

// 3-way bf16 split: v = h + m + l + e, |e| <= 2^-27 |v|
__device__ __forceinline__ void split3(float v, __nv_bfloat16& h,
                                       __nv_bfloat16& m, __nv_bfloat16& l) {
    h = __float2bfloat16(v);
    float r1 = v - __bfloat162float(h);
    m = __float2bfloat16(r1);
    float r2 = r1 - __bfloat162float(m);
    l = __float2bfloat16(r2);
}

// ---------------- GEMM (bf16 3-split, dual tensor acc + fp32 master) -------
__global__ void __launch_bounds__(256, 1)
mma_gemm(const __nv_bfloat16* __restrict__ Ah, const __nv_bfloat16* __restrict__ Am,
         const __nv_bfloat16* __restrict__ Al,
         const __nv_bfloat16* __restrict__ Bh, const __nv_bfloat16* __restrict__ Bm,
         const __nv_bfloat16* __restrict__ Bl,
         const float* __restrict__ bias, float* __restrict__ C,
         int Kpad, int Nact, int nst)
{
    extern __shared__ char smem[];
    const int tid  = threadIdx.x;
    const int wid  = tid >> 5;
    const int lane = tid & 31;
    const int m0   = blockIdx.y * BM;
    const int n0   = blockIdx.x * BNT;
    const uint32_t sb = smem_u32(smem);

    const int wm = wid & 3;           // 0..3  -> m offset wm*32
    const int wn = wid >> 2;          // 0..1  -> n offset wn*32

    float acc_hi[2][4][4], acc_lo[2][4][4], master[2][4][4];
#pragma unroll
    for (int i = 0; i < 2; i++)
#pragma unroll
        for (int j = 0; j < 4; j++)
#pragma unroll
            for (int k = 0; k < 4; k++) {
                acc_hi[i][j][k] = 0.f; acc_lo[i][j][k] = 0.f; master[i][j][k] = 0.f;
            }

    // ldmatrix lane-address components
    const int a_row  = lane & 15;
    const int a_koff = (lane >> 4) << 3;
    const int b_nr   = (lane & 7) + ((lane >> 4) << 3);
    const int b_koff = ((lane >> 3) & 1) << 3;

    // ---- stage loader: 9 x cp.async.16B per thread ----
    auto load_stage = [&](int s, int k0) {
        uint32_t st = sb + s * STAGE_BYTES;
#pragma unroll
        for (int i = 0; i < 2; i++) {                 // A: 128 rows x 4 granules
            int g = tid + i * 256;
            int row = g >> 2, gc = g & 3;
            size_t  go = (size_t)(m0 + row) * Kpad + k0 + gc * 8;
            uint32_t so = row * (SMS * 2) + gc * 16;
            cp16(st + OFF_AH + so, Ah + go);
            cp16(st + OFF_AM + so, Am + go);
            cp16(st + OFF_AL + so, Al + go);
        }
        {                                             // B: 64 rows x 4 granules
            int row = tid >> 2, gc = tid & 3;
            size_t  go = (size_t)(n0 + row) * Kpad + k0 + gc * 8;
            uint32_t so = row * (SMS * 2) + gc * 16;
            cp16(st + OFF_BH + so, Bh + go);
            cp16(st + OFF_BM + so, Bm + go);
            cp16(st + OFF_BL + so, Bl + go);
        }
    };

    load_stage(0, 0);
    cp_commit();

    for (int s = 0; s < nst; s++) {
        if (s + 1 < nst) {
            load_stage((s + 1) & 1, (s + 1) * BK);
            cp_commit();
            cp_wait1();
        } else {
            cp_wait0();
        }
        __syncthreads();

        uint32_t st = sb + (s & 1) * STAGE_BYTES;
#pragma unroll
        for (int kb = 0; kb < BK; kb += 16) {
            uint32_t ah[2][4], am[2][4], al[2][4];
#pragma unroll
            for (int mt = 0; mt < 2; mt++) {
                uint32_t ro = (uint32_t)(wm * 32 + mt * 16 + a_row) * (SMS * 2)
                            + (uint32_t)(kb + a_koff) * 2;
                ldsm4(ah[mt], st + OFF_AH + ro);
                ldsm4(am[mt], st + OFF_AM + ro);
                ldsm4(al[mt], st + OFF_AL + ro);
            }
            uint32_t bh[4][2], bm[4][2], bl[4][2];
#pragma unroll
            for (int p = 0; p < 2; p++) {
                uint32_t ro = (uint32_t)(wn * 32 + p * 16 + b_nr) * (SMS * 2)
                            + (uint32_t)(kb + b_koff) * 2;
                uint32_t r[4];
                ldsm4(r, st + OFF_BH + ro);
                bh[p*2][0] = r[0]; bh[p*2][1] = r[1];
                bh[p*2+1][0] = r[2]; bh[p*2+1][1] = r[3];
                ldsm4(r, st + OFF_BM + ro);
                bm[p*2][0] = r[0]; bm[p*2][1] = r[1];
                bm[p*2+1][0] = r[2]; bm[p*2+1][1] = r[3];
                ldsm4(r, st + OFF_BL + ro);
                bl[p*2][0] = r[0]; bl[p*2][1] = r[1];
                bl[p*2+1][0] = r[2]; bl[p*2+1][1] = r[3];
            }
#pragma unroll
            for (int mt = 0; mt < 2; mt++)
#pragma unroll
                for (int nt = 0; nt < 4; nt++) {
                    // big term -> acc_hi
                    mma_bf16(acc_hi[mt][nt], ah[mt], bh[nt]);
                    // small terms -> acc_lo (stay inside tensor-acc
                    // alignment window because acc_lo is ~2^-9 scale)
                    mma_bf16(acc_lo[mt][nt], ah[mt], bm[nt]);
                    mma_bf16(acc_lo[mt][nt], am[mt], bh[nt]);
                    mma_bf16(acc_lo[mt][nt], am[mt], bm[nt]);
                    mma_bf16(acc_lo[mt][nt], ah[mt], bl[nt]);
                    mma_bf16(acc_lo[mt][nt], al[mt], bh[nt]);
                }
        }

        // fold tensor accumulators into fp32 master to bound RZ bias
        if ((s & 7) == 7 || s == nst - 1) {
#pragma unroll
            for (int mt = 0; mt < 2; mt++)
#pragma unroll
                for (int nt = 0; nt < 4; nt++)
#pragma unroll
                    for (int k = 0; k < 4; k++) {
                        master[mt][nt][k] += acc_hi[mt][nt][k] + acc_lo[mt][nt][k];
                        acc_hi[mt][nt][k] = 0.f;
                        acc_lo[mt][nt][k] = 0.f;
                    }
        }
        __syncthreads();
    }

    // ---- epilogue: add bias, store fp32 ----
    const int er = lane >> 2;
    const int ec = (lane & 3) * 2;
#pragma unroll
    for (int mt = 0; mt < 2; mt++) {
        int row = m0 + wm * 32 + mt * 16 + er;
#pragma unroll
        for (int nt = 0; nt < 4; nt++) {
            int col = n0 + wn * 32 + nt * 8 + ec;
            float* c = master[mt][nt];
            if (col < Nact) {
                float b0 = bias[col];
                C[(size_t)row * Nact + col]       = c[0] + b0;
                C[(size_t)(row + 8) * Nact + col] = c[2] + b0;
                if (col + 1 < Nact) {
                    float b1 = bias[col + 1];
                    C[(size_t)row * Nact + col + 1]       = c[1] + b1;
                    C[(size_t)(row + 8) * Nact + col + 1] = c[3] + b1;
                }
            }
        }
    }
}

// ---------------- fp32 SIMT GEMM (head only) --------------------------------
#define FBM 128
#define FBN 128
#define FBK 16
__global__ void __launch_bounds__(256)
gemm_bias_f32(const float* __restrict__ A, const float* __restrict__ W,
              const float* __restrict__ bias, float* __restrict__ C,
              int M, int N, int K)
{
    __shared__ float As[FBK][FBM];
    __shared__ float Ws[FBK][FBN];
    const int tid = threadIdx.x;
    const int m0  = blockIdx.y * FBM;
    const int n0  = blockIdx.x * FBN;
    const int tm  = (tid / 16) * 8;
    const int tn  = (tid % 16) * 8;

    float acc[8][8];
#pragma unroll
    for (int i = 0; i < 8; i++)
#pragma unroll
        for (int j = 0; j < 8; j++) acc[i][j] = 0.f;

    for (int k0 = 0; k0 < K; k0 += FBK) {
#pragma unroll
        for (int i = 0; i < 8; i++) {
            int idx = i * 256 + tid;
            int r = idx / FBK, kk = idx % FBK;
            int gm = m0 + r, gk = k0 + kk;
            As[kk][r] = (gm < M && gk < K) ? A[(size_t)gm * K + gk] : 0.f;
        }
#pragma unroll
        for (int i = 0; i < 8; i++) {
            int idx = i * 256 + tid;
            int kk = idx / FBN, c = idx % FBN;
            int gk = k0 + kk, gn = n0 + c;
            Ws[kk][c] = (gk < K && gn < N) ? W[(size_t)gk * N + gn] : 0.f;
        }
        __syncthreads();
#pragma unroll
        for (int kk = 0; kk < FBK; kk++) {
            float ra[8], rb[8];
            const float4* a4 = reinterpret_cast<const float4*>(&As[kk][tm]);
            float4 av0 = a4[0], av1 = a4[1];
            ra[0]=av0.x; ra[1]=av0.y; ra[2]=av0.z; ra[3]=av0.w;
            ra[4]=av1.x; ra[5]=av1.y; ra[6]=av1.z; ra[7]=av1.w;
            const float4* b4 = reinterpret_cast<const float4*>(&Ws[kk][tn]);
            float4 bv0 = b4[0], bv1 = b4[1];
            rb[0]=bv0.x; rb[1]=bv0.y; rb[2]=bv0.z; rb[3]=bv0.w;
            rb[4]=bv1.x; rb[5]=bv1.y; rb[6]=bv1.z; rb[7]=bv1.w;
#pragma unroll
            for (int i = 0; i < 8; i++)
#pragma unroll
                for (int j = 0; j < 8; j++)
                    acc[i][j] = fmaf(ra[i], rb[j], acc[i][j]);
        }
        __syncthreads();
    }
#pragma unroll
    for (int i = 0; i < 8; i++) {
        int gm = m0 + tm + i;
        if (gm >= M) continue;
#pragma unroll
        for (int j = 0; j < 8; j++) {
            int gn = n0 + tn + j;
            if (gn < N) C[(size_t)gm * N + gn] = acc[i][j] + bias[gn];
        }
    }
}

// ---------------- conversions ----------------------------------------------
__global__ void split_pad_kernel(const float* __restrict__ X,
                                 __nv_bfloat16* __restrict__ Xh,
                                 __nv_bfloat16* __restrict__ Xm,
                                 __nv_bfloat16* __restrict__ Xl,
                                 int M, int K, int Kpad)
{
    size_t idx = (size_t)blockIdx.x * blockDim.x + threadIdx.x;
    if (idx >= (size_t)M * Kpad) return;
    int row = (int)(idx / Kpad), col = (int)(idx % Kpad);
    float v = (col < K) ? X[(size_t)row * K + col] : 0.f;
    __nv_bfloat16 h, m, l;
    split3(v, h, m, l);
    Xh[idx] = h; Xm[idx] = m; Xl[idx] = l;
}

__global__ void transpose_split_kernel(const float* __restrict__ W,
                                       __nv_bfloat16* __restrict__ Wh,
                                       __nv_bfloat16* __restrict__ Wm,
                                       __nv_bfloat16* __restrict__ Wl,
                                       int K, int N, int Kpad)
{
    __shared__ float t[32][33];
    int kb = blockIdx.x * 32, nb = blockIdx.y * 32;
    int tx = threadIdx.x, ty = threadIdx.y;   // block (32,8)
#pragma unroll
    for (int yy = 0; yy < 4; yy++) {
        int k = kb + ty + yy * 8, n = nb + tx;
        t[ty + yy * 8][tx] = (k < K && n < N) ? W[(size_t)k * N + n] : 0.f;
    }
    __syncthreads();
#pragma unroll
    for (int yy = 0; yy < 4; yy++) {
        int n = nb + ty + yy * 8, k = kb + tx;
        float v = t[tx][ty + yy * 8];
        __nv_bfloat16 h, m, l;
        split3(v, h, m, l);
        size_t o = (size_t)n * Kpad + k;
        Wh[o] = h; Wm[o] = m; Wl[o] = l;
    }
}

// ---------------- batchnorm ------------------------------------------------
__global__ void bn_stats_kernel(const float* __restrict__ X,
                                const float* __restrict__ gamma,
                                const float* __restrict__ beta,
                                float* __restrict__ scale,
                                float* __restrict__ shift,
                                int M, int N)
{
    int lane = threadIdx.x % 32;
    int ry   = threadIdx.x / 32;
    int col  = blockIdx.x * 32 + lane;
    float s = 0.f, q = 0.f;
    for (int r = ry; r < M; r += 8) {
        float v = X[(size_t)r * N + col];
        s += v; q += v * v;
    }
    __shared__ float ss[8][33], sq[8][33];
    ss[ry][lane] = s; sq[ry][lane] = q;
    __syncthreads();
    if (ry == 0) {
#pragma unroll
        for (int i = 1; i < 8; i++) { s += ss[i][lane]; q += sq[i][lane]; }
        float inv = 1.f / (float)M;
        float mu  = s * inv;
        float var = q * inv - mu * mu;
        float rs  = rsqrtf(var + BN_EPS);
        float sc  = gamma[col] * rs;
        scale[col] = sc;
        shift[col] = beta[col] - mu * sc;
    }
}

__global__ void bn_apply_split_kernel(const float* __restrict__ X,
                                      const float* __restrict__ scale,
                                      const float* __restrict__ shift,
                                      const float* __restrict__ res,
                                      float* __restrict__ Yf,
                                      __nv_bfloat16* __restrict__ Yh,
                                      __nv_bfloat16* __restrict__ Ym,
                                      __nv_bfloat16* __restrict__ Yl,
                                      int total4, int N)
{
    int i = blockIdx.x * blockDim.x + threadIdx.x;
    if (i >= total4) return;
    int c0 = (i * 4) & (N - 1);
    float4 x = reinterpret_cast<const float4*>(X)[i];
    float4 o;
    o.x = x.x * scale[c0 + 0] + shift[c0 + 0];
    o.y = x.y * scale[c0 + 1] + shift[c0 + 1];
    o.z = x.z * scale[c0 + 2] + shift[c0 + 2];
    o.w = x.w * scale[c0 + 3] + shift[c0 + 3];
    if (res) {
        float4 h = reinterpret_cast<const float4*>(res)[i];
        o.x += h.x; o.y += h.y; o.z += h.z; o.w += h.w;
    }
    o.x = fmaxf(o.x, 0.f); o.y = fmaxf(o.y, 0.f);
    o.z = fmaxf(o.z, 0.f); o.w = fmaxf(o.w, 0.f);
    if (Yf) reinterpret_cast<float4*>(Yf)[i] = o;

    if (Yh) {
        float v[4] = {o.x, o.y, o.z, o.w};
        __nv_bfloat16 h4[4], m4[4], l4[4];
#pragma unroll
        for (int k = 0; k < 4; k++) split3(v[k], h4[k], m4[k], l4[k]);
        reinterpret_cast<uint2*>(Yh)[i] = *reinterpret_cast<uint2*>(h4);
        reinterpret_cast<uint2*>(Ym)[i] = *reinterpret_cast<uint2*>(m4);
        reinterpret_cast<uint2*>(Yl)[i] = *reinterpret_cast<uint2*>(l4);
    }
}

// ---------------- polar factor of 3x3 (replaces SVD U@Vh) ------------------
__global__ void polar_kernel(const float* __restrict__ O,
                             float* __restrict__ out, int B)
{
    int i = blockIdx.x * blockDim.x + threadIdx.x;
    if (i >= B * 24) return;
    int b = i / 24, j = i % 24;
    const float* m = O + (size_t)b * OUT_DIM + j * 9;
    float X[9];
#pragma unroll
    for (int k = 0; k < 9; k++) X[k] = m[k];
#pragma unroll
    for (int it = 0; it < 14; it++) {
        float C0 = X[4]*X[8] - X[5]*X[7];
        float C1 = X[5]*X[6] - X[3]*X[8];
        float C2 = X[3]*X[7] - X[4]*X[6];
        float C3 = X[2]*X[7] - X[1]*X[8];
        float C4 = X[0]*X[8] - X[2]*X[6];
        float C5 = X[1]*X[6] - X[0]*X[7];
        float C6 = X[1]*X[5] - X[2]*X[4];
        float C7 = X[2]*X[3] - X[0]*X[5];
        float C8 = X[0]*X[4] - X[1]*X[3];
        float d  = X[0]*C0 + X[1]*C1 + X[2]*C2;
        float ad = fmaxf(fabsf(d), 1e-30f);
        float g  = 1.f / cbrtf(ad);
        float c2 = copysignf(g * g, d);
        X[0] = 0.5f*(g*X[0] + c2*C0);
        X[1] = 0.5f*(g*X[1] + c2*C1);
        X[2] = 0.5f*(g*X[2] + c2*C2);
        X[3] = 0.5f*(g*X[3] + c2*C3);
        X[4] = 0.5f*(g*X[4] + c2*C4);
        X[5] = 0.5f*(g*X[5] + c2*C5);
        X[6] = 0.5f*(g*X[6] + c2*C6);
        X[7] = 0.5f*(g*X[7] + c2*C7);
        X[8] = 0.5f*(g*X[8] + c2*C8);
    }
    float det = X[0]*(X[4]*X[8]-X[5]*X[7])
              - X[1]*(X[3]*X[8]-X[5]*X[6])
              + X[2]*(X[3]*X[7]-X[4]*X[6]);
    float s = (det >= 0.f) ? 1.f : -1.f;
    float* dst = out + (size_t)i * 9;
#pragma unroll
    for (int k = 0; k < 9; k++) dst[k] = X[k] * s;
}

__global__ void tail_kernel(const float* __restrict__ O,
                            float* __restrict__ out, int B)
{
    int i = blockIdx.x * blockDim.x + threadIdx.x;
    if (i >= B * 13) return;
    int b = i / 13, t = i % 13;
    size_t betas_off  = (size_t)B * 216;
    size_t camera_off = betas_off + (size_t)B * 10;
    if (t < 10)
        out[betas_off + (size_t)b * 10 + t] = O[(size_t)b * OUT_DIM + 216 + t];
    else
        out[camera_off + (size_t)b * 3 + (t - 10)] = O[(size_t)b * OUT_DIM + 226 + (t - 10)];
}

// ---------------------------------------------------------------------------
static void launch_gemm(const __nv_bfloat16* Ah, const __nv_bfloat16* Am,
                        const __nv_bfloat16* Al,
                        const __nv_bfloat16* Bh, const __nv_bfloat16* Bm,
                        const __nv_bfloat16* Bl,
                        const float* bias, float* C, int Kpad)
{
    dim3 grid(H_DIM / BNT, B_BATCH / BM);
    mma_gemm<<<grid, 256, SMEM_REQ>>>(Ah, Am, Al, Bh, Bm, Bl, bias, C,
                                      Kpad, H_DIM, Kpad / BK);
}

static void launch_bn(const float* X, const float* g, const float* be,
                      float* scale, float* shift,
                      const float* res, float* Yf,
                      __nv_bfloat16* Yh, __nv_bfloat16* Ym, __nv_bfloat16* Yl)
{
    bn_stats_kernel<<<H_DIM / 32, 256>>>(X, g, be, scale, shift, B_BATCH, H_DIM);
    int total4 = B_BATCH * H_DIM / 4;
    bn_apply_split_kernel<<<(total4 + 255) / 256, 256>>>(X, scale, shift, res,
                                                         Yf, Yh, Ym, Yl, total4, H_DIM);
}

extern "C" void kernel_launch(void* const* d_in, const int* in_sizes, int n_in,
                              void* d_out, int out_size)
{
    const float* x    = (const float*)d_in[0];
    const float* w1   = (const float*)d_in[1];
    const float* b1   = (const float*)d_in[2];
    const float* g1   = (const float*)d_in[3];
    const float* be1  = (const float*)d_in[4];
    const float* w2a  = (const float*)d_in[5];
    const float* b2a  = (const float*)d_in[6];
    const float* g2a  = (const float*)d_in[7];
    const float* be2a = (const float*)d_in[8];
    const float* w2b  = (const float*)d_in[9];
    const float* b2b  = (const float*)d_in[10];
    const float* g2b  = (const float*)d_in[11];
    const float* be2b = (const float*)d_in[12];
    const float* w3a  = (const float*)d_in[13];
    const float* b3a  = (const float*)d_in[14];
    const float* g3a  = (const float*)d_in[15];
    const float* be3a = (const float*)d_in[16];
    const float* w3b  = (const float*)d_in[17];
    const float* b3b  = (const float*)d_in[18];
    const float* g3b  = (const float*)d_in[19];
    const float* be3b = (const float*)d_in[20];
    const float* w4   = (const float*)d_in[21];
    const float* b4   = (const float*)d_in[22];
    float* out = (float*)d_out;

    cudaFuncSetAttribute(mma_gemm, cudaFuncAttributeMaxDynamicSharedMemorySize,
                         SMEM_REQ);

    float *A, *H0, *H1, *O4, *sc, *sh;
    __nv_bfloat16 *Xh, *Xm, *Xl, *AhB, *AmB, *AlB;
    __nv_bfloat16 *W1h, *W1m, *W1l, *W2ah, *W2am, *W2al, *W2bh, *W2bm, *W2bl;
    __nv_bfloat16 *W3ah, *W3am, *W3al, *W3bh, *W3bm, *W3bl;
    cudaGetSymbolAddress((void**)&A,  g_A);
    cudaGetSymbolAddress((void**)&H0, g_H0);
    cudaGetSymbolAddress((void**)&H1, g_H1);
    cudaGetSymbolAddress((void**)&O4, g_O4);
    cudaGetSymbolAddress((void**)&sc, g_scale);
    cudaGetSymbolAddress((void**)&sh, g_shift);
    cudaGetSymbolAddress((void**)&Xh, g_Xh);
    cudaGetSymbolAddress((void**)&Xm, g_Xm);
    cudaGetSymbolAddress((void**)&Xl, g_Xl);
    cudaGetSymbolAddress((void**)&AhB, g_Ah);
    cudaGetSymbolAddress((void**)&AmB, g_Am);
    cudaGetSymbolAddress((void**)&AlB, g_Al);
    cudaGetSymbolAddress((void**)&W1h, g_W1h);   cudaGetSymbolAddress((void**)&W1m, g_W1m);
    cudaGetSymbolAddress((void**)&W1l, g_W1l);
    cudaGetSymbolAddress((void**)&W2ah, g_W2ah); cudaGetSymbolAddress((void**)&W2am, g_W2am);
    cudaGetSymbolAddress((void**)&W2al, g_W2al);
    cudaGetSymbolAddress((void**)&W2bh, g_W2bh); cudaGetSymbolAddress((void**)&W2bm, g_W2bm);
    cudaGetSymbolAddress((void**)&W2bl, g_W2bl);
    cudaGetSymbolAddress((void**)&W3ah, g_W3ah); cudaGetSymbolAddress((void**)&W3am, g_W3am);
    cudaGetSymbolAddress((void**)&W3al, g_W3al);
    cudaGetSymbolAddress((void**)&W3bh, g_W3bh); cudaGetSymbolAddress((void**)&W3bm, g_W3bm);
    cudaGetSymbolAddress((void**)&W3bl, g_W3bl);

    // --- conversions -------------------------------------------------------
    {
        size_t tot = (size_t)B_BATCH * IN_PAD;
        split_pad_kernel<<<(unsigned)((tot + 255) / 256), 256>>>(x, Xh, Xm, Xl,
                                                                 B_BATCH, IN_DIM, IN_PAD);
        dim3 blk(32, 8);
        transpose_split_kernel<<<dim3(IN_PAD / 32, H_DIM / 32), blk>>>(w1, W1h, W1m, W1l, IN_DIM, H_DIM, IN_PAD);
        transpose_split_kernel<<<dim3(H_DIM / 32, H_DIM / 32), blk>>>(w2a, W2ah, W2am, W2al, H_DIM, H_DIM, H_DIM);
        transpose_split_kernel<<<dim3(H_DIM / 32, H_DIM / 32), blk>>>(w2b, W2bh, W2bm, W2bl, H_DIM, H_DIM, H_DIM);
        transpose_split_kernel<<<dim3(H_DIM / 32, H_DIM / 32), blk>>>(w3a, W3ah, W3am, W3al, H_DIM, H_DIM, H_DIM);
        transpose_split_kernel<<<dim3(H_DIM / 32, H_DIM / 32), blk>>>(w3b, W3bh, W3bm, W3bl, H_DIM, H_DIM, H_DIM);
    }

    // --- layer 1 -----------------------------------------------------------
    launch_gemm(Xh, Xm, Xl, W1h, W1m, W1l, b1, A, IN_PAD);
    launch_bn(A, g1, be1, sc, sh, nullptr, H0, AhB, AmB, AlB);

    // --- resblock 2 --------------------------------------------------------
    launch_gemm(AhB, AmB, AlB, W2ah, W2am, W2al, b2a, A, H_DIM);
    launch_bn(A, g2a, be2a, sc, sh, nullptr, nullptr, AhB, AmB, AlB);
    launch_gemm(AhB, AmB, AlB, W2bh, W2bm, W2bl, b2b, A, H_DIM);
    launch_bn(A, g2b, be2b, sc, sh, H0, H1, AhB, AmB, AlB);

    // --- resblock 3 --------------------------------------------------------
    launch_gemm(AhB, AmB, AlB, W3ah, W3am, W3al, b3a, A, H_DIM);
    launch_bn(A, g3a, be3a, sc, sh, nullptr, nullptr, AhB, AmB, AlB);
    launch_gemm(AhB, AmB, AlB, W3bh, W3bm, W3bl, b3b, A, H_DIM);
    launch_bn(A, g3b, be3b, sc, sh, H1, H0, nullptr, nullptr, nullptr);

    // --- output head (fp32 SIMT — feeds the flip-sensitive polar stage) ----
    {
        dim3 grid((OUT_DIM + FBN - 1) / FBN, B_BATCH / FBM);
        gemm_bias_f32<<<grid, 256>>>(H0, w4, b4, O4, B_BATCH, OUT_DIM, H_DIM);
    }

    // --- polar + tail ------------------------------------------------------
    int nmat = B_BATCH * 24;
    polar_kernel<<<(nmat + 127) / 128, 128>>>(O4, out, B_BATCH);
    int ntail = B_BATCH * 13;
    tail_kernel<<<(ntail + 255) / 256, 256>>>(O4, out, B_BATCH);
}

// round 6
// speedup vs baseline: 1.4957x; 1.1503x over previous
#include <cuda_runtime.h>
#include <cuda_bf16.h>
#include <math.h>
#include <stdint.h>

#define B_BATCH 4096
#define H_DIM   1024
#define IN_DIM  10338
#define IN_PAD  10368
#define OUT_DIM 229
#define BN_EPS  1e-5f

// ---------------- MMA GEMM tiling -------------------------------------------
#define BM 128
#define BNT 64
#define BK 64                               // K per stage (doubled vs R5)
#define SMS 72                              // smem row stride in bf16 (144B, conflict-free)
#define A_CB (BM * SMS * 2)                 // 18432 bytes per class
#define B_CB (BNT * SMS * 2)                // 9216 bytes per class
#define OFF_AH 0
#define OFF_AM (A_CB)
#define OFF_AL (2 * A_CB)
#define OFF_BH (3 * A_CB)
#define OFF_BM (3 * A_CB + B_CB)
#define OFF_BL (3 * A_CB + 2 * B_CB)
#define STAGE_BYTES (3 * A_CB + 3 * B_CB)   // 82944
#define SMEM_REQ (2 * STAGE_BYTES)          // 165888

// ---------------- scratch (device globals; no allocation allowed) ----------
__device__ float g_A [(size_t)B_BATCH * H_DIM];
__device__ float g_H0[(size_t)B_BATCH * H_DIM];
__device__ float g_H1[(size_t)B_BATCH * H_DIM];
__device__ float g_O4[(size_t)B_BATCH * OUT_DIM];
__device__ float g_scale[H_DIM];
__device__ float g_shift[H_DIM];

__device__ __nv_bfloat16 g_Xh[(size_t)B_BATCH * IN_PAD];
__device__ __nv_bfloat16 g_Xm[(size_t)B_BATCH * IN_PAD];
__device__ __nv_bfloat16 g_Xl[(size_t)B_BATCH * IN_PAD];
__device__ __nv_bfloat16 g_Ah[(size_t)B_BATCH * H_DIM];
__device__ __nv_bfloat16 g_Am[(size_t)B_BATCH * H_DIM];
__device__ __nv_bfloat16 g_Al[(size_t)B_BATCH * H_DIM];

__device__ __nv_bfloat16 g_W1h[(size_t)H_DIM * IN_PAD];
__device__ __nv_bfloat16 g_W1m[(size_t)H_DIM * IN_PAD];
__device__ __nv_bfloat16 g_W1l[(size_t)H_DIM * IN_PAD];
__device__ __nv_bfloat16 g_W2ah[(size_t)H_DIM * H_DIM];
__device__ __nv_bfloat16 g_W2am[(size_t)H_DIM * H_DIM];
__device__ __nv_bfloat16 g_W2al[(size_t)H_DIM * H_DIM];
__device__ __nv_bfloat16 g_W2bh[(size_t)H_DIM * H_DIM];
__device__ __nv_bfloat16 g_W2bm[(size_t)H_DIM * H_DIM];
__device__ __nv_bfloat16 g_W2bl[(size_t)H_DIM * H_DIM];
__device__ __nv_bfloat16 g_W3ah[(size_t)H_DIM * H_DIM];
__device__ __nv_bfloat16 g_W3am[(size_t)H_DIM * H_DIM];
__device__ __nv_bfloat16 g_W3al[(size_t)H_DIM * H_DIM];
__device__ __nv_bfloat16 g_W3bh[(size_t)H_DIM * H_DIM];
__device__ __nv_bfloat16 g_W3bm[(size_t)H_DIM * H_DIM];
__device__ __nv_bfloat16 g_W3bl[(size_t)H_DIM * H_DIM];

// ---------------- PTX helpers (baseline PTX; no sm_103a features) ----------
__device__ __forceinline__ uint32_t smem_u32(const void* p) {
    uint32_t a;
    asm("{ .reg .u64 t; cvta.to.shared.u64 t, %1; cvt.u32.u64 %0, t; }"
        : "=r"(a) : "l"(p));
    return a;
}
__device__ __forceinline__ void cp16(uint32_t dst, const void* src) {
    asm volatile("cp.async.cg.shared.global [%0], [%1], 16;" :: "r"(dst), "l"(src));
}
__device__ __forceinline__ void cp_commit() { asm volatile("cp.async.commit_group;" ::: "memory"); }
__device__ __forceinline__ void cp_wait1()  { asm volatile("cp.async.wait_group 1;" ::: "memory"); }
__device__ __forceinline__ void cp_wait0()  { asm volatile("cp.async.wait_group 0;" ::: "memory"); }

__device__ __forceinline__ void ldsm4(uint32_t r[4], uint32_t addr) {
    asm volatile("ldmatrix.sync.aligned.m8n8.x4.shared.b16 {%0,%1,%2,%3}, [%4];"
                 : "=r"(r[0]), "=r"(r[1]), "=r"(r[2]), "=r"(r[3]) : "r"(addr));
}
__device__ __forceinline__ void mma_bf16(float c[4], const uint32_t a[4],
                                         const uint32_t b[2]) {
    asm volatile(
        "mma.sync.aligned.m16n8k16.row.col.f32.bf16.bf16.f32 "
        "{%0,%1,%2,%3}, {%4,%5,%6,%7}, {%8,%9}, {%0,%1,%2,%3};"
        : "+f"(c[0]), "+f"(c[1]), "+f"(c[2]), "+f"(c[3])
        : "r"(a[0]), "r"(a[1]), "r"(a[2]), "r"(a[3]), "r"(b[0]), "r"(b[1]));
}

// 3-way bf16 split: v = h + m + l + e, |e| <= 2^-27 |v|
__device__ __forceinline__ void split3(float v, __nv_bfloat16& h,
                                       __nv_bfloat16& m, __nv_bfloat16& l) {
    h = __float2bfloat16(v);
    float r1 = v - __bfloat162float(h);
    m = __float2bfloat16(r1);
    float r2 = r1 - __bfloat162float(m);
    l = __float2bfloat16(r2);
}

// ---------------- GEMM (bf16 3-split, dual tensor acc + fp32 master) -------
__global__ void __launch_bounds__(256, 1)
mma_gemm(const __nv_bfloat16* __restrict__ Ah, const __nv_bfloat16* __restrict__ Am,
         const __nv_bfloat16* __restrict__ Al,
         const __nv_bfloat16* __restrict__ Bh, const __nv_bfloat16* __restrict__ Bm,
         const __nv_bfloat16* __restrict__ Bl,
         const float* __restrict__ bias, float* __restrict__ C,
         int Kpad, int Nact, int nst)
{
    extern __shared__ char smem[];
    const int tid  = threadIdx.x;
    const int wid  = tid >> 5;
    const int lane = tid & 31;
    const int m0   = blockIdx.y * BM;
    const int n0   = blockIdx.x * BNT;
    const uint32_t sb = smem_u32(smem);

    const int wm = wid & 3;           // 0..3  -> m offset wm*32
    const int wn = wid >> 2;          // 0..1  -> n offset wn*32

    float acc_hi[2][4][4], acc_lo[2][4][4], master[2][4][4];
#pragma unroll
    for (int i = 0; i < 2; i++)
#pragma unroll
        for (int j = 0; j < 4; j++)
#pragma unroll
            for (int k = 0; k < 4; k++) {
                acc_hi[i][j][k] = 0.f; acc_lo[i][j][k] = 0.f; master[i][j][k] = 0.f;
            }

    // ldmatrix lane-address components
    const int a_row  = lane & 15;
    const int a_koff = (lane >> 4) << 3;
    const int b_nr   = (lane & 7) + ((lane >> 4) << 3);
    const int b_koff = ((lane >> 3) & 1) << 3;

    // per-warp smem row bases (bytes), hoisted
    const uint32_t a_rb0 = (uint32_t)(wm * 32 + a_row) * (SMS * 2) + a_koff * 2;
    const uint32_t a_rb1 = a_rb0 + 16 * (SMS * 2);
    const uint32_t b_rb0 = (uint32_t)(wn * 32 + b_nr) * (SMS * 2) + b_koff * 2;
    const uint32_t b_rb1 = b_rb0 + 16 * (SMS * 2);

    // ---- stage loader: 18 x cp.async.16B per thread ----
    auto load_stage = [&](int s, int k0) {
        uint32_t st = sb + s * STAGE_BYTES;
#pragma unroll
        for (int i = 0; i < 4; i++) {                 // A: 128 rows x 8 granules
            int g = tid + i * 256;
            int row = g >> 3, gc = g & 7;
            size_t  go = (size_t)(m0 + row) * Kpad + k0 + gc * 8;
            uint32_t so = row * (SMS * 2) + gc * 16;
            cp16(st + OFF_AH + so, Ah + go);
            cp16(st + OFF_AM + so, Am + go);
            cp16(st + OFF_AL + so, Al + go);
        }
#pragma unroll
        for (int i = 0; i < 2; i++) {                 // B: 64 rows x 8 granules
            int g = tid + i * 256;
            int row = g >> 3, gc = g & 7;
            size_t  go = (size_t)(n0 + row) * Kpad + k0 + gc * 8;
            uint32_t so = row * (SMS * 2) + gc * 16;
            cp16(st + OFF_BH + so, Bh + go);
            cp16(st + OFF_BM + so, Bm + go);
            cp16(st + OFF_BL + so, Bl + go);
        }
    };

    load_stage(0, 0);
    cp_commit();
    load_stage(1, BK);
    cp_commit();

    for (int s = 0; s < nst; s++) {
        if (s + 1 < nst) cp_wait1(); else cp_wait0();
        __syncthreads();

        uint32_t st = sb + (s & 1) * STAGE_BYTES;
#pragma unroll
        for (int kb = 0; kb < BK; kb += 16) {
            const uint32_t kbo = (uint32_t)kb * 2;
            uint32_t ah[2][4], am[2][4], al[2][4];
            ldsm4(ah[0], st + OFF_AH + a_rb0 + kbo);
            ldsm4(am[0], st + OFF_AM + a_rb0 + kbo);
            ldsm4(al[0], st + OFF_AL + a_rb0 + kbo);
            ldsm4(ah[1], st + OFF_AH + a_rb1 + kbo);
            ldsm4(am[1], st + OFF_AM + a_rb1 + kbo);
            ldsm4(al[1], st + OFF_AL + a_rb1 + kbo);

            uint32_t bh[4][2], bm[4][2], bl[4][2];
#pragma unroll
            for (int p = 0; p < 2; p++) {
                uint32_t ro = (p ? b_rb1 : b_rb0) + kbo;
                uint32_t r[4];
                ldsm4(r, st + OFF_BH + ro);
                bh[p*2][0] = r[0]; bh[p*2][1] = r[1];
                bh[p*2+1][0] = r[2]; bh[p*2+1][1] = r[3];
                ldsm4(r, st + OFF_BM + ro);
                bm[p*2][0] = r[0]; bm[p*2][1] = r[1];
                bm[p*2+1][0] = r[2]; bm[p*2+1][1] = r[3];
                ldsm4(r, st + OFF_BL + ro);
                bl[p*2][0] = r[0]; bl[p*2][1] = r[1];
                bl[p*2+1][0] = r[2]; bl[p*2+1][1] = r[3];
            }
#pragma unroll
            for (int mt = 0; mt < 2; mt++)
#pragma unroll
                for (int nt = 0; nt < 4; nt++) {
                    mma_bf16(acc_hi[mt][nt], ah[mt], bh[nt]);
                    mma_bf16(acc_lo[mt][nt], ah[mt], bm[nt]);
                    mma_bf16(acc_lo[mt][nt], am[mt], bh[nt]);
                    mma_bf16(acc_lo[mt][nt], am[mt], bm[nt]);
                    mma_bf16(acc_lo[mt][nt], ah[mt], bl[nt]);
                    mma_bf16(acc_lo[mt][nt], al[mt], bh[nt]);
                }
        }

        // fold tensor accumulators into fp32 master every 256 K (same as R5)
        if ((s & 3) == 3 || s == nst - 1) {
#pragma unroll
            for (int mt = 0; mt < 2; mt++)
#pragma unroll
                for (int nt = 0; nt < 4; nt++)
#pragma unroll
                    for (int k = 0; k < 4; k++) {
                        master[mt][nt][k] += acc_hi[mt][nt][k] + acc_lo[mt][nt][k];
                        acc_hi[mt][nt][k] = 0.f;
                        acc_lo[mt][nt][k] = 0.f;
                    }
        }
        __syncthreads();
        if (s + 2 < nst) {
            load_stage(s & 1, (s + 2) * BK);
            cp_commit();
        }
    }

    // ---- epilogue: add bias, store fp32 ----
    const int er = lane >> 2;
    const int ec = (lane & 3) * 2;
#pragma unroll
    for (int mt = 0; mt < 2; mt++) {
        int row = m0 + wm * 32 + mt * 16 + er;
#pragma unroll
        for (int nt = 0; nt < 4; nt++) {
            int col = n0 + wn * 32 + nt * 8 + ec;
            float* c = master[mt][nt];
            if (col < Nact) {
                float b0 = bias[col];
                C[(size_t)row * Nact + col]       = c[0] + b0;
                C[(size_t)(row + 8) * Nact + col] = c[2] + b0;
                if (col + 1 < Nact) {
                    float b1 = bias[col + 1];
                    C[(size_t)row * Nact + col + 1]       = c[1] + b1;
                    C[(size_t)(row + 8) * Nact + col + 1] = c[3] + b1;
                }
            }
        }
    }
}

// ---------------- fp32 SIMT GEMM (head only) --------------------------------
#define FBM 128
#define FBN 128
#define FBK 16
__global__ void __launch_bounds__(256)
gemm_bias_f32(const float* __restrict__ A, const float* __restrict__ W,
              const float* __restrict__ bias, float* __restrict__ C,
              int M, int N, int K)
{
    __shared__ float As[FBK][FBM];
    __shared__ float Ws[FBK][FBN];
    const int tid = threadIdx.x;
    const int m0  = blockIdx.y * FBM;
    const int n0  = blockIdx.x * FBN;
    const int tm  = (tid / 16) * 8;
    const int tn  = (tid % 16) * 8;

    float acc[8][8];
#pragma unroll
    for (int i = 0; i < 8; i++)
#pragma unroll
        for (int j = 0; j < 8; j++) acc[i][j] = 0.f;

    for (int k0 = 0; k0 < K; k0 += FBK) {
#pragma unroll
        for (int i = 0; i < 8; i++) {
            int idx = i * 256 + tid;
            int r = idx / FBK, kk = idx % FBK;
            int gm = m0 + r, gk = k0 + kk;
            As[kk][r] = (gm < M && gk < K) ? A[(size_t)gm * K + gk] : 0.f;
        }
#pragma unroll
        for (int i = 0; i < 8; i++) {
            int idx = i * 256 + tid;
            int kk = idx / FBN, c = idx % FBN;
            int gk = k0 + kk, gn = n0 + c;
            Ws[kk][c] = (gk < K && gn < N) ? W[(size_t)gk * N + gn] : 0.f;
        }
        __syncthreads();
#pragma unroll
        for (int kk = 0; kk < FBK; kk++) {
            float ra[8], rb[8];
            const float4* a4 = reinterpret_cast<const float4*>(&As[kk][tm]);
            float4 av0 = a4[0], av1 = a4[1];
            ra[0]=av0.x; ra[1]=av0.y; ra[2]=av0.z; ra[3]=av0.w;
            ra[4]=av1.x; ra[5]=av1.y; ra[6]=av1.z; ra[7]=av1.w;
            const float4* b4 = reinterpret_cast<const float4*>(&Ws[kk][tn]);
            float4 bv0 = b4[0], bv1 = b4[1];
            rb[0]=bv0.x; rb[1]=bv0.y; rb[2]=bv0.z; rb[3]=bv0.w;
            rb[4]=bv1.x; rb[5]=bv1.y; rb[6]=bv1.z; rb[7]=bv1.w;
#pragma unroll
            for (int i = 0; i < 8; i++)
#pragma unroll
                for (int j = 0; j < 8; j++)
                    acc[i][j] = fmaf(ra[i], rb[j], acc[i][j]);
        }
        __syncthreads();
    }
#pragma unroll
    for (int i = 0; i < 8; i++) {
        int gm = m0 + tm + i;
        if (gm >= M) continue;
#pragma unroll
        for (int j = 0; j < 8; j++) {
            int gn = n0 + tn + j;
            if (gn < N) C[(size_t)gm * N + gn] = acc[i][j] + bias[gn];
        }
    }
}

// ---------------- conversions ----------------------------------------------
__global__ void split_pad_kernel(const float* __restrict__ X,
                                 __nv_bfloat16* __restrict__ Xh,
                                 __nv_bfloat16* __restrict__ Xm,
                                 __nv_bfloat16* __restrict__ Xl,
                                 int M, int K, int Kpad)
{
    size_t idx = (size_t)blockIdx.x * blockDim.x + threadIdx.x;
    if (idx >= (size_t)M * Kpad) return;
    int row = (int)(idx / Kpad), col = (int)(idx % Kpad);
    float v = (col < K) ? X[(size_t)row * K + col] : 0.f;
    __nv_bfloat16 h, m, l;
    split3(v, h, m, l);
    Xh[idx] = h; Xm[idx] = m; Xl[idx] = l;
}

__global__ void transpose_split_kernel(const float* __restrict__ W,
                                       __nv_bfloat16* __restrict__ Wh,
                                       __nv_bfloat16* __restrict__ Wm,
                                       __nv_bfloat16* __restrict__ Wl,
                                       int K, int N, int Kpad)
{
    __shared__ float t[32][33];
    int kb = blockIdx.x * 32, nb = blockIdx.y * 32;
    int tx = threadIdx.x, ty = threadIdx.y;   // block (32,8)
#pragma unroll
    for (int yy = 0; yy < 4; yy++) {
        int k = kb + ty + yy * 8, n = nb + tx;
        t[ty + yy * 8][tx] = (k < K && n < N) ? W[(size_t)k * N + n] : 0.f;
    }
    __syncthreads();
#pragma unroll
    for (int yy = 0; yy < 4; yy++) {
        int n = nb + ty + yy * 8, k = kb + tx;
        float v = t[tx][ty + yy * 8];
        __nv_bfloat16 h, m, l;
        split3(v, h, m, l);
        size_t o = (size_t)n * Kpad + k;
        Wh[o] = h; Wm[o] = m; Wl[o] = l;
    }
}

// ---------------- batchnorm ------------------------------------------------
__global__ void bn_stats_kernel(const float* __restrict__ X,
                                const float* __restrict__ gamma,
                                const float* __restrict__ beta,
                                float* __restrict__ scale,
                                float* __restrict__ shift,
                                int M, int N)
{
    int lane = threadIdx.x % 32;
    int ry   = threadIdx.x / 32;
    int col  = blockIdx.x * 32 + lane;
    float s = 0.f, q = 0.f;
    for (int r = ry; r < M; r += 8) {
        float v = X[(size_t)r * N + col];
        s += v; q += v * v;
    }
    __shared__ float ss[8][33], sq[8][33];
    ss[ry][lane] = s; sq[ry][lane] = q;
    __syncthreads();
    if (ry == 0) {
#pragma unroll
        for (int i = 1; i < 8; i++) { s += ss[i][lane]; q += sq[i][lane]; }
        float inv = 1.f / (float)M;
        float mu  = s * inv;
        float var = q * inv - mu * mu;
        float rs  = rsqrtf(var + BN_EPS);
        float sc  = gamma[col] * rs;
        scale[col] = sc;
        shift[col] = beta[col] - mu * sc;
    }
}

__global__ void bn_apply_split_kernel(const float* __restrict__ X,
                                      const float* __restrict__ scale,
                                      const float* __restrict__ shift,
                                      const float* __restrict__ res,
                                      float* __restrict__ Yf,
                                      __nv_bfloat16* __restrict__ Yh,
                                      __nv_bfloat16* __restrict__ Ym,
                                      __nv_bfloat16* __restrict__ Yl,
                                      int total4, int N)
{
    int i = blockIdx.x * blockDim.x + threadIdx.x;
    if (i >= total4) return;
    int c0 = (i * 4) & (N - 1);
    float4 x = reinterpret_cast<const float4*>(X)[i];
    float4 o;
    o.x = x.x * scale[c0 + 0] + shift[c0 + 0];
    o.y = x.y * scale[c0 + 1] + shift[c0 + 1];
    o.z = x.z * scale[c0 + 2] + shift[c0 + 2];
    o.w = x.w * scale[c0 + 3] + shift[c0 + 3];
    if (res) {
        float4 h = reinterpret_cast<const float4*>(res)[i];
        o.x += h.x; o.y += h.y; o.z += h.z; o.w += h.w;
    }
    o.x = fmaxf(o.x, 0.f); o.y = fmaxf(o.y, 0.f);
    o.z = fmaxf(o.z, 0.f); o.w = fmaxf(o.w, 0.f);
    if (Yf) reinterpret_cast<float4*>(Yf)[i] = o;

    if (Yh) {
        float v[4] = {o.x, o.y, o.z, o.w};
        __nv_bfloat16 h4[4], m4[4], l4[4];
#pragma unroll
        for (int k = 0; k < 4; k++) split3(v[k], h4[k], m4[k], l4[k]);
        reinterpret_cast<uint2*>(Yh)[i] = *reinterpret_cast<uint2*>(h4);
        reinterpret_cast<uint2*>(Ym)[i] = *reinterpret_cast<uint2*>(m4);
        reinterpret_cast<uint2*>(Yl)[i] = *reinterpret_cast<uint2*>(l4);
    }
}

// ---------------- polar factor of 3x3 (replaces SVD U@Vh) ------------------
__global__ void polar_kernel(const float* __restrict__ O,
                             float* __restrict__ out, int B)
{
    int i = blockIdx.x * blockDim.x + threadIdx.x;
    if (i >= B * 24) return;
    int b = i / 24, j = i % 24;
    const float* m = O + (size_t)b * OUT_DIM + j * 9;
    float X[9];
#pragma unroll
    for (int k = 0; k < 9; k++) X[k] = m[k];
#pragma unroll
    for (int it = 0; it < 14; it++) {
        float C0 = X[4]*X[8] - X[5]*X[7];
        float C1 = X[5]*X[6] - X[3]*X[8];
        float C2 = X[3]*X[7] - X[4]*X[6];
        float C3 = X[2]*X[7] - X[1]*X[8];
        float C4 = X[0]*X[8] - X[2]*X[6];
        float C5 = X[1]*X[6] - X[0]*X[7];
        float C6 = X[1]*X[5] - X[2]*X[4];
        float C7 = X[2]*X[3] - X[0]*X[5];
        float C8 = X[0]*X[4] - X[1]*X[3];
        float d  = X[0]*C0 + X[1]*C1 + X[2]*C2;
        float ad = fmaxf(fabsf(d), 1e-30f);
        float g  = 1.f / cbrtf(ad);
        float c2 = copysignf(g * g, d);
        X[0] = 0.5f*(g*X[0] + c2*C0);
        X[1] = 0.5f*(g*X[1] + c2*C1);
        X[2] = 0.5f*(g*X[2] + c2*C2);
        X[3] = 0.5f*(g*X[3] + c2*C3);
        X[4] = 0.5f*(g*X[4] + c2*C4);
        X[5] = 0.5f*(g*X[5] + c2*C5);
        X[6] = 0.5f*(g*X[6] + c2*C6);
        X[7] = 0.5f*(g*X[7] + c2*C7);
        X[8] = 0.5f*(g*X[8] + c2*C8);
    }
    float det = X[0]*(X[4]*X[8]-X[5]*X[7])
              - X[1]*(X[3]*X[8]-X[5]*X[6])
              + X[2]*(X[3]*X[7]-X[4]*X[6]);
    float s = (det >= 0.f) ? 1.f : -1.f;
    float* dst = out + (size_t)i * 9;
#pragma unroll
    for (int k = 0; k < 9; k++) dst[k] = X[k] * s;
}

__global__ void tail_kernel(const float* __restrict__ O,
                            float* __restrict__ out, int B)
{
    int i = blockIdx.x * blockDim.x + threadIdx.x;
    if (i >= B * 13) return;
    int b = i / 13, t = i % 13;
    size_t betas_off  = (size_t)B * 216;
    size_t camera_off = betas_off + (size_t)B * 10;
    if (t < 10)
        out[betas_off + (size_t)b * 10 + t] = O[(size_t)b * OUT_DIM + 216 + t];
    else
        out[camera_off + (size_t)b * 3 + (t - 10)] = O[(size_t)b * OUT_DIM + 226 + (t - 10)];
}

// ---------------------------------------------------------------------------
static void launch_gemm(const __nv_bfloat16* Ah, const __nv_bfloat16* Am,
                        const __nv_bfloat16* Al,
                        const __nv_bfloat16* Bh, const __nv_bfloat16* Bm,
                        const __nv_bfloat16* Bl,
                        const float* bias, float* C, int Kpad)
{
    dim3 grid(H_DIM / BNT, B_BATCH / BM);
    mma_gemm<<<grid, 256, SMEM_REQ>>>(Ah, Am, Al, Bh, Bm, Bl, bias, C,
                                      Kpad, H_DIM, Kpad / BK);
}

static void launch_bn(const float* X, const float* g, const float* be,
                      float* scale, float* shift,
                      const float* res, float* Yf,
                      __nv_bfloat16* Yh, __nv_bfloat16* Ym, __nv_bfloat16* Yl)
{
    bn_stats_kernel<<<H_DIM / 32, 256>>>(X, g, be, scale, shift, B_BATCH, H_DIM);
    int total4 = B_BATCH * H_DIM / 4;
    bn_apply_split_kernel<<<(total4 + 255) / 256, 256>>>(X, scale, shift, res,
                                                         Yf, Yh, Ym, Yl, total4, H_DIM);
}

extern "C" void kernel_launch(void* const* d_in, const int* in_sizes, int n_in,
                              void* d_out, int out_size)
{
    const float* x    = (const float*)d_in[0];
    const float* w1   = (const float*)d_in[1];
    const float* b1   = (const float*)d_in[2];
    const float* g1   = (const float*)d_in[3];
    const float* be1  = (const float*)d_in[4];
    const float* w2a  = (const float*)d_in[5];
    const float* b2a  = (const float*)d_in[6];
    const float* g2a  = (const float*)d_in[7];
    const float* be2a = (const float*)d_in[8];
    const float* w2b  = (const float*)d_in[9];
    const float* b2b  = (const float*)d_in[10];
    const float* g2b  = (const float*)d_in[11];
    const float* be2b = (const float*)d_in[12];
    const float* w3a  = (const float*)d_in[13];
    const float* b3a  = (const float*)d_in[14];
    const float* g3a  = (const float*)d_in[15];
    const float* be3a = (const float*)d_in[16];
    const float* w3b  = (const float*)d_in[17];
    const float* b3b  = (const float*)d_in[18];
    const float* g3b  = (const float*)d_in[19];
    const float* be3b = (const float*)d_in[20];
    const float* w4   = (const float*)d_in[21];
    const float* b4   = (const float*)d_in[22];
    float* out = (float*)d_out;

    cudaFuncSetAttribute(mma_gemm, cudaFuncAttributeMaxDynamicSharedMemorySize,
                         SMEM_REQ);

    float *A, *H0, *H1, *O4, *sc, *sh;
    __nv_bfloat16 *Xh, *Xm, *Xl, *AhB, *AmB, *AlB;
    __nv_bfloat16 *W1h, *W1m, *W1l, *W2ah, *W2am, *W2al, *W2bh, *W2bm, *W2bl;
    __nv_bfloat16 *W3ah, *W3am, *W3al, *W3bh, *W3bm, *W3bl;
    cudaGetSymbolAddress((void**)&A,  g_A);
    cudaGetSymbolAddress((void**)&H0, g_H0);
    cudaGetSymbolAddress((void**)&H1, g_H1);
    cudaGetSymbolAddress((void**)&O4, g_O4);
    cudaGetSymbolAddress((void**)&sc, g_scale);
    cudaGetSymbolAddress((void**)&sh, g_shift);
    cudaGetSymbolAddress((void**)&Xh, g_Xh);
    cudaGetSymbolAddress((void**)&Xm, g_Xm);
    cudaGetSymbolAddress((void**)&Xl, g_Xl);
    cudaGetSymbolAddress((void**)&AhB, g_Ah);
    cudaGetSymbolAddress((void**)&AmB, g_Am);
    cudaGetSymbolAddress((void**)&AlB, g_Al);
    cudaGetSymbolAddress((void**)&W1h, g_W1h);   cudaGetSymbolAddress((void**)&W1m, g_W1m);
    cudaGetSymbolAddress((void**)&W1l, g_W1l);
    cudaGetSymbolAddress((void**)&W2ah, g_W2ah); cudaGetSymbolAddress((void**)&W2am, g_W2am);
    cudaGetSymbolAddress((void**)&W2al, g_W2al);
    cudaGetSymbolAddress((void**)&W2bh, g_W2bh); cudaGetSymbolAddress((void**)&W2bm, g_W2bm);
    cudaGetSymbolAddress((void**)&W2bl, g_W2bl);
    cudaGetSymbolAddress((void**)&W3ah, g_W3ah); cudaGetSymbolAddress((void**)&W3am, g_W3am);
    cudaGetSymbolAddress((void**)&W3al, g_W3al);
    cudaGetSymbolAddress((void**)&W3bh, g_W3bh); cudaGetSymbolAddress((void**)&W3bm, g_W3bm);
    cudaGetSymbolAddress((void**)&W3bl, g_W3bl);

    // --- conversions -------------------------------------------------------
    {
        size_t tot = (size_t)B_BATCH * IN_PAD;
        split_pad_kernel<<<(unsigned)((tot + 255) / 256), 256>>>(x, Xh, Xm, Xl,
                                                                 B_BATCH, IN_DIM, IN_PAD);
        dim3 blk(32, 8);
        transpose_split_kernel<<<dim3(IN_PAD / 32, H_DIM / 32), blk>>>(w1, W1h, W1m, W1l, IN_DIM, H_DIM, IN_PAD);
        transpose_split_kernel<<<dim3(H_DIM / 32, H_DIM / 32), blk>>>(w2a, W2ah, W2am, W2al, H_DIM, H_DIM, H_DIM);
        transpose_split_kernel<<<dim3(H_DIM / 32, H_DIM / 32), blk>>>(w2b, W2bh, W2bm, W2bl, H_DIM, H_DIM, H_DIM);
        transpose_split_kernel<<<dim3(H_DIM / 32, H_DIM / 32), blk>>>(w3a, W3ah, W3am, W3al, H_DIM, H_DIM, H_DIM);
        transpose_split_kernel<<<dim3(H_DIM / 32, H_DIM / 32), blk>>>(w3b, W3bh, W3bm, W3bl, H_DIM, H_DIM, H_DIM);
    }

    // --- layer 1 -----------------------------------------------------------
    launch_gemm(Xh, Xm, Xl, W1h, W1m, W1l, b1, A, IN_PAD);
    launch_bn(A, g1, be1, sc, sh, nullptr, H0, AhB, AmB, AlB);

    // --- resblock 2 --------------------------------------------------------
    launch_gemm(AhB, AmB, AlB, W2ah, W2am, W2al, b2a, A, H_DIM);
    launch_bn(A, g2a, be2a, sc, sh, nullptr, nullptr, AhB, AmB, AlB);
    launch_gemm(AhB, AmB, AlB, W2bh, W2bm, W2bl, b2b, A, H_DIM);
    launch_bn(A, g2b, be2b, sc, sh, H0, H1, AhB, AmB, AlB);

    // --- resblock 3 --------------------------------------------------------
    launch_gemm(AhB, AmB, AlB, W3ah, W3am, W3al, b3a, A, H_DIM);
    launch_bn(A, g3a, be3a, sc, sh, nullptr, nullptr, AhB, AmB, AlB);
    launch_gemm(AhB, AmB, AlB, W3bh, W3bm, W3bl, b3b, A, H_DIM);
    launch_bn(A, g3b, be3b, sc, sh, H1, H0, nullptr, nullptr, nullptr);

    // --- output head (fp32 SIMT — feeds the flip-sensitive polar stage) ----
    {
        dim3 grid((OUT_DIM + FBN - 1) / FBN, B_BATCH / FBM);
        gemm_bias_f32<<<grid, 256>>>(H0, w4, b4, O4, B_BATCH, OUT_DIM, H_DIM);
    }

    // --- polar + tail ------------------------------------------------------
    int nmat = B_BATCH * 24;
    polar_kernel<<<(nmat + 127) / 128, 128>>>(O4, out, B_BATCH);
    int ntail = B_BATCH * 13;
    tail_kernel<<<(ntail + 255) / 256, 256>>>(O4, out, B_BATCH);
}

// round 7
// speedup vs baseline: 2.0984x; 1.4030x over previous
#include <cuda_runtime.h>
#include <cuda_fp16.h>
#include <math.h>
#include <stdint.h>

#define B_BATCH 4096
#define H_DIM   1024
#define IN_DIM  10338
#define IN_PAD  10368
#define OUT_DIM 229
#define BN_EPS  1e-5f
#define WSCALE    512.0f
#define INV_WSCALE (1.0f / 512.0f)

// ---------------- MMA GEMM tiling -------------------------------------------
#define BM 128
#define BNT 64
#define BK 64
#define SMS 72                              // smem row stride in fp16 (144B)
#define A_CB (BM * SMS * 2)                 // 18432 bytes per class
#define B_CB (BNT * SMS * 2)                // 9216 bytes per class
#define OFF_AH 0
#define OFF_AL (A_CB)
#define OFF_BH (2 * A_CB)
#define OFF_BL (2 * A_CB + B_CB)
#define STAGE_BYTES (2 * A_CB + 2 * B_CB)   // 55296
#define NSTAGE 3
#define SMEM_REQ (NSTAGE * STAGE_BYTES)     // 165888

#define BN_CH 16                            // bn stats row chunks

// ---------------- scratch (device globals; no allocation allowed) ----------
__device__ float g_A [(size_t)B_BATCH * H_DIM];
__device__ float g_H0[(size_t)B_BATCH * H_DIM];
__device__ float g_H1[(size_t)B_BATCH * H_DIM];
__device__ float g_O4[(size_t)B_BATCH * OUT_DIM];
__device__ float g_scale[H_DIM];
__device__ float g_shift[H_DIM];
__device__ float g_psum[BN_CH * H_DIM];
__device__ float g_psq [BN_CH * H_DIM];

__device__ __half g_Xh[(size_t)B_BATCH * IN_PAD];
__device__ __half g_Xl[(size_t)B_BATCH * IN_PAD];
__device__ __half g_Ah[(size_t)B_BATCH * H_DIM];
__device__ __half g_Al[(size_t)B_BATCH * H_DIM];

__device__ __half g_W1h[(size_t)H_DIM * IN_PAD];
__device__ __half g_W1l[(size_t)H_DIM * IN_PAD];
__device__ __half g_W2ah[(size_t)H_DIM * H_DIM];
__device__ __half g_W2al[(size_t)H_DIM * H_DIM];
__device__ __half g_W2bh[(size_t)H_DIM * H_DIM];
__device__ __half g_W2bl[(size_t)H_DIM * H_DIM];
__device__ __half g_W3ah[(size_t)H_DIM * H_DIM];
__device__ __half g_W3al[(size_t)H_DIM * H_DIM];
__device__ __half g_W3bh[(size_t)H_DIM * H_DIM];
__device__ __half g_W3bl[(size_t)H_DIM * H_DIM];

// ---------------- PTX helpers (baseline PTX; no sm_103a features) ----------
__device__ __forceinline__ uint32_t smem_u32(const void* p) {
    uint32_t a;
    asm("{ .reg .u64 t; cvta.to.shared.u64 t, %1; cvt.u32.u64 %0, t; }"
        : "=r"(a) : "l"(p));
    return a;
}
__device__ __forceinline__ void cp16(uint32_t dst, const void* src) {
    asm volatile("cp.async.cg.shared.global [%0], [%1], 16;" :: "r"(dst), "l"(src));
}
__device__ __forceinline__ void cp_commit() { asm volatile("cp.async.commit_group;" ::: "memory"); }
__device__ __forceinline__ void cp_wait2()  { asm volatile("cp.async.wait_group 2;" ::: "memory"); }
__device__ __forceinline__ void cp_wait1()  { asm volatile("cp.async.wait_group 1;" ::: "memory"); }
__device__ __forceinline__ void cp_wait0()  { asm volatile("cp.async.wait_group 0;" ::: "memory"); }

__device__ __forceinline__ void ldsm4(uint32_t r[4], uint32_t addr) {
    asm volatile("ldmatrix.sync.aligned.m8n8.x4.shared.b16 {%0,%1,%2,%3}, [%4];"
                 : "=r"(r[0]), "=r"(r[1]), "=r"(r[2]), "=r"(r[3]) : "r"(addr));
}
__device__ __forceinline__ void mma_f16(float c[4], const uint32_t a[4],
                                        const uint32_t b[2]) {
    asm volatile(
        "mma.sync.aligned.m16n8k16.row.col.f32.f16.f16.f32 "
        "{%0,%1,%2,%3}, {%4,%5,%6,%7}, {%8,%9}, {%0,%1,%2,%3};"
        : "+f"(c[0]), "+f"(c[1]), "+f"(c[2]), "+f"(c[3])
        : "r"(a[0]), "r"(a[1]), "r"(a[2]), "r"(a[3]), "r"(b[0]), "r"(b[1]));
}

// 2-way fp16 split: v = h + l + e, |e| <= 2^-22 |v| (for normal-range l)
__device__ __forceinline__ void split2(float v, __half& h, __half& l) {
    h = __float2half_rn(v);
    l = __float2half_rn(v - __half2float(h));
}

// ---------------- GEMM (fp16 2-split, 4-term, dual acc + fp32 master) ------
__global__ void __launch_bounds__(256, 1)
mma_gemm(const __half* __restrict__ Ah, const __half* __restrict__ Al,
         const __half* __restrict__ Bh, const __half* __restrict__ Bl,
         const float* __restrict__ bias, float* __restrict__ C,
         int Kpad, int Nact, int nst, float outScale)
{
    extern __shared__ char smem[];
    const int tid  = threadIdx.x;
    const int wid  = tid >> 5;
    const int lane = tid & 31;
    const int m0   = blockIdx.y * BM;
    const int n0   = blockIdx.x * BNT;
    const uint32_t sb = smem_u32(smem);

    const int wm = wid & 3;           // 0..3  -> m offset wm*32
    const int wn = wid >> 2;          // 0..1  -> n offset wn*32

    float acc_hi[2][4][4], acc_lo[2][4][4], master[2][4][4];
#pragma unroll
    for (int i = 0; i < 2; i++)
#pragma unroll
        for (int j = 0; j < 4; j++)
#pragma unroll
            for (int k = 0; k < 4; k++) {
                acc_hi[i][j][k] = 0.f; acc_lo[i][j][k] = 0.f; master[i][j][k] = 0.f;
            }

    // ldmatrix lane-address components
    const int a_row  = lane & 15;
    const int a_koff = (lane >> 4) << 3;
    const int b_nr   = (lane & 7) + ((lane >> 4) << 3);
    const int b_koff = ((lane >> 3) & 1) << 3;

    const uint32_t a_rb0 = (uint32_t)(wm * 32 + a_row) * (SMS * 2) + a_koff * 2;
    const uint32_t a_rb1 = a_rb0 + 16 * (SMS * 2);
    const uint32_t b_rb0 = (uint32_t)(wn * 32 + b_nr) * (SMS * 2) + b_koff * 2;
    const uint32_t b_rb1 = b_rb0 + 16 * (SMS * 2);

    // ---- stage loader: 12 x cp.async.16B per thread ----
    auto load_stage = [&](int s, int k0) {
        uint32_t st = sb + s * STAGE_BYTES;
#pragma unroll
        for (int i = 0; i < 4; i++) {                 // A: 128 rows x 8 granules
            int g = tid + i * 256;
            int row = g >> 3, gc = g & 7;
            size_t  go = (size_t)(m0 + row) * Kpad + k0 + gc * 8;
            uint32_t so = row * (SMS * 2) + gc * 16;
            cp16(st + OFF_AH + so, Ah + go);
            cp16(st + OFF_AL + so, Al + go);
        }
#pragma unroll
        for (int i = 0; i < 2; i++) {                 // B: 64 rows x 8 granules
            int g = tid + i * 256;
            int row = g >> 3, gc = g & 7;
            size_t  go = (size_t)(n0 + row) * Kpad + k0 + gc * 8;
            uint32_t so = row * (SMS * 2) + gc * 16;
            cp16(st + OFF_BH + so, Bh + go);
            cp16(st + OFF_BL + so, Bl + go);
        }
    };

    // prologue: fill 3 stages
#pragma unroll
    for (int i = 0; i < NSTAGE; i++) {
        if (i < nst) load_stage(i, i * BK);
        cp_commit();
    }

    int buf = 0;
    for (int s = 0; s < nst; s++) {
        if (s + 2 < nst)      cp_wait2();
        else if (s + 1 < nst) cp_wait1();
        else                  cp_wait0();
        __syncthreads();

        uint32_t st = sb + buf * STAGE_BYTES;
#pragma unroll
        for (int kb = 0; kb < BK; kb += 16) {
            const uint32_t kbo = (uint32_t)kb * 2;
            uint32_t ah[2][4], al[2][4];
            ldsm4(ah[0], st + OFF_AH + a_rb0 + kbo);
            ldsm4(al[0], st + OFF_AL + a_rb0 + kbo);
            ldsm4(ah[1], st + OFF_AH + a_rb1 + kbo);
            ldsm4(al[1], st + OFF_AL + a_rb1 + kbo);

            uint32_t bh[4][2], bl[4][2];
#pragma unroll
            for (int p = 0; p < 2; p++) {
                uint32_t ro = (p ? b_rb1 : b_rb0) + kbo;
                uint32_t r[4];
                ldsm4(r, st + OFF_BH + ro);
                bh[p*2][0] = r[0]; bh[p*2][1] = r[1];
                bh[p*2+1][0] = r[2]; bh[p*2+1][1] = r[3];
                ldsm4(r, st + OFF_BL + ro);
                bl[p*2][0] = r[0]; bl[p*2][1] = r[1];
                bl[p*2+1][0] = r[2]; bl[p*2+1][1] = r[3];
            }
#pragma unroll
            for (int mt = 0; mt < 2; mt++)
#pragma unroll
                for (int nt = 0; nt < 4; nt++) {
                    mma_f16(acc_hi[mt][nt], ah[mt], bh[nt]);   // ~1
                    mma_f16(acc_lo[mt][nt], ah[mt], bl[nt]);   // ~2^-11
                    mma_f16(acc_lo[mt][nt], al[mt], bh[nt]);   // ~2^-11
                    mma_f16(acc_lo[mt][nt], al[mt], bl[nt]);   // ~2^-22
                }
        }

        // fold tensor accumulators into fp32 master every 256 K
        if ((s & 3) == 3 || s == nst - 1) {
#pragma unroll
            for (int mt = 0; mt < 2; mt++)
#pragma unroll
                for (int nt = 0; nt < 4; nt++)
#pragma unroll
                    for (int k = 0; k < 4; k++) {
                        master[mt][nt][k] += acc_hi[mt][nt][k] + acc_lo[mt][nt][k];
                        acc_hi[mt][nt][k] = 0.f;
                        acc_lo[mt][nt][k] = 0.f;
                    }
        }
        __syncthreads();
        if (s + NSTAGE < nst) {
            load_stage(buf, (s + NSTAGE) * BK);
            cp_commit();
        } else {
            cp_commit();   // keep group counting consistent
        }
        buf = (buf + 1 == NSTAGE) ? 0 : buf + 1;
    }

    // ---- epilogue: unscale, add bias, store fp32 ----
    const int er = lane >> 2;
    const int ec = (lane & 3) * 2;
#pragma unroll
    for (int mt = 0; mt < 2; mt++) {
        int row = m0 + wm * 32 + mt * 16 + er;
#pragma unroll
        for (int nt = 0; nt < 4; nt++) {
            int col = n0 + wn * 32 + nt * 8 + ec;
            float* c = master[mt][nt];
            if (col < Nact) {
                float b0 = bias[col];
                C[(size_t)row * Nact + col]       = c[0] * outScale + b0;
                C[(size_t)(row + 8) * Nact + col] = c[2] * outScale + b0;
                if (col + 1 < Nact) {
                    float b1 = bias[col + 1];
                    C[(size_t)row * Nact + col + 1]       = c[1] * outScale + b1;
                    C[(size_t)(row + 8) * Nact + col + 1] = c[3] * outScale + b1;
                }
            }
        }
    }
}

// ---------------- fp32 SIMT GEMM (head only) --------------------------------
#define FBM 128
#define FBN 128
#define FBK 16
__global__ void __launch_bounds__(256)
gemm_bias_f32(const float* __restrict__ A, const float* __restrict__ W,
              const float* __restrict__ bias, float* __restrict__ C,
              int M, int N, int K)
{
    __shared__ float As[FBK][FBM];
    __shared__ float Ws[FBK][FBN];
    const int tid = threadIdx.x;
    const int m0  = blockIdx.y * FBM;
    const int n0  = blockIdx.x * FBN;
    const int tm  = (tid / 16) * 8;
    const int tn  = (tid % 16) * 8;

    float acc[8][8];
#pragma unroll
    for (int i = 0; i < 8; i++)
#pragma unroll
        for (int j = 0; j < 8; j++) acc[i][j] = 0.f;

    for (int k0 = 0; k0 < K; k0 += FBK) {
#pragma unroll
        for (int i = 0; i < 8; i++) {
            int idx = i * 256 + tid;
            int r = idx / FBK, kk = idx % FBK;
            int gm = m0 + r, gk = k0 + kk;
            As[kk][r] = (gm < M && gk < K) ? A[(size_t)gm * K + gk] : 0.f;
        }
#pragma unroll
        for (int i = 0; i < 8; i++) {
            int idx = i * 256 + tid;
            int kk = idx / FBN, c = idx % FBN;
            int gk = k0 + kk, gn = n0 + c;
            Ws[kk][c] = (gk < K && gn < N) ? W[(size_t)gk * N + gn] : 0.f;
        }
        __syncthreads();
#pragma unroll
        for (int kk = 0; kk < FBK; kk++) {
            float ra[8], rb[8];
            const float4* a4 = reinterpret_cast<const float4*>(&As[kk][tm]);
            float4 av0 = a4[0], av1 = a4[1];
            ra[0]=av0.x; ra[1]=av0.y; ra[2]=av0.z; ra[3]=av0.w;
            ra[4]=av1.x; ra[5]=av1.y; ra[6]=av1.z; ra[7]=av1.w;
            const float4* b4 = reinterpret_cast<const float4*>(&Ws[kk][tn]);
            float4 bv0 = b4[0], bv1 = b4[1];
            rb[0]=bv0.x; rb[1]=bv0.y; rb[2]=bv0.z; rb[3]=bv0.w;
            rb[4]=bv1.x; rb[5]=bv1.y; rb[6]=bv1.z; rb[7]=bv1.w;
#pragma unroll
            for (int i = 0; i < 8; i++)
#pragma unroll
                for (int j = 0; j < 8; j++)
                    acc[i][j] = fmaf(ra[i], rb[j], acc[i][j]);
        }
        __syncthreads();
    }
#pragma unroll
    for (int i = 0; i < 8; i++) {
        int gm = m0 + tm + i;
        if (gm >= M) continue;
#pragma unroll
        for (int j = 0; j < 8; j++) {
            int gn = n0 + tn + j;
            if (gn < N) C[(size_t)gm * N + gn] = acc[i][j] + bias[gn];
        }
    }
}

// ---------------- conversions ----------------------------------------------
__global__ void split_pad_kernel(const float* __restrict__ X,
                                 __half* __restrict__ Xh,
                                 __half* __restrict__ Xl,
                                 int M, int K, int Kpad)
{
    size_t idx = (size_t)blockIdx.x * blockDim.x + threadIdx.x;
    if (idx >= (size_t)M * Kpad) return;
    int row = (int)(idx / Kpad), col = (int)(idx % Kpad);
    float v = (col < K) ? X[(size_t)row * K + col] : 0.f;
    __half h, l;
    split2(v, h, l);
    Xh[idx] = h; Xl[idx] = l;
}

// fp32 W[K,N] -> fp16 h/l of (W^T * WSCALE) [Npad,Kpad]
__global__ void transpose_split_kernel(const float* __restrict__ W,
                                       __half* __restrict__ Wh,
                                       __half* __restrict__ Wl,
                                       int K, int N, int Kpad)
{
    __shared__ float t[32][33];
    int kb = blockIdx.x * 32, nb = blockIdx.y * 32;
    int tx = threadIdx.x, ty = threadIdx.y;   // block (32,8)
#pragma unroll
    for (int yy = 0; yy < 4; yy++) {
        int k = kb + ty + yy * 8, n = nb + tx;
        t[ty + yy * 8][tx] = (k < K && n < N) ? W[(size_t)k * N + n] : 0.f;
    }
    __syncthreads();
#pragma unroll
    for (int yy = 0; yy < 4; yy++) {
        int n = nb + ty + yy * 8, k = kb + tx;
        float v = t[tx][ty + yy * 8] * WSCALE;
        __half h, l;
        split2(v, h, l);
        size_t o = (size_t)n * Kpad + k;
        Wh[o] = h; Wl[o] = l;
    }
}

// ---------------- batchnorm (two-phase stats) -------------------------------
__global__ void bn_stats_part(const float* __restrict__ X,
                              float* __restrict__ psum, float* __restrict__ psq,
                              int M, int N)
{
    int lane  = threadIdx.x & 31;
    int ry    = threadIdx.x >> 5;           // 0..7
    int col   = blockIdx.x * 32 + lane;
    int chunk = blockIdx.y;
    int rows  = M / BN_CH;                  // 256
    int r0    = chunk * rows;
    float s = 0.f, q = 0.f;
    for (int r = r0 + ry; r < r0 + rows; r += 8) {
        float v = X[(size_t)r * N + col];
        s += v; q += v * v;
    }
    __shared__ float ss[8][33], sq[8][33];
    ss[ry][lane] = s; sq[ry][lane] = q;
    __syncthreads();
    if (ry == 0) {
#pragma unroll
        for (int i = 1; i < 8; i++) { s += ss[i][lane]; q += sq[i][lane]; }
        psum[chunk * N + col] = s;
        psq [chunk * N + col] = q;
    }
}

__global__ void bn_stats_final(const float* __restrict__ psum,
                               const float* __restrict__ psq,
                               const float* __restrict__ gamma,
                               const float* __restrict__ beta,
                               float* __restrict__ scale,
                               float* __restrict__ shift,
                               int N, int M)
{
    int col = blockIdx.x * blockDim.x + threadIdx.x;
    if (col >= N) return;
    float s = 0.f, q = 0.f;
#pragma unroll
    for (int c = 0; c < BN_CH; c++) { s += psum[c * N + col]; q += psq[c * N + col]; }
    float inv = 1.f / (float)M;
    float mu  = s * inv;
    float var = q * inv - mu * mu;
    float rs  = rsqrtf(var + BN_EPS);
    float sc  = gamma[col] * rs;
    scale[col] = sc;
    shift[col] = beta[col] - mu * sc;
}

__global__ void bn_apply_split_kernel(const float* __restrict__ X,
                                      const float* __restrict__ scale,
                                      const float* __restrict__ shift,
                                      const float* __restrict__ res,
                                      float* __restrict__ Yf,
                                      __half* __restrict__ Yh,
                                      __half* __restrict__ Yl,
                                      int total4, int N)
{
    int i = blockIdx.x * blockDim.x + threadIdx.x;
    if (i >= total4) return;
    int c0 = (i * 4) & (N - 1);
    float4 x = reinterpret_cast<const float4*>(X)[i];
    float4 o;
    o.x = x.x * scale[c0 + 0] + shift[c0 + 0];
    o.y = x.y * scale[c0 + 1] + shift[c0 + 1];
    o.z = x.z * scale[c0 + 2] + shift[c0 + 2];
    o.w = x.w * scale[c0 + 3] + shift[c0 + 3];
    if (res) {
        float4 h = reinterpret_cast<const float4*>(res)[i];
        o.x += h.x; o.y += h.y; o.z += h.z; o.w += h.w;
    }
    o.x = fmaxf(o.x, 0.f); o.y = fmaxf(o.y, 0.f);
    o.z = fmaxf(o.z, 0.f); o.w = fmaxf(o.w, 0.f);
    if (Yf) reinterpret_cast<float4*>(Yf)[i] = o;

    if (Yh) {
        float v[4] = {o.x, o.y, o.z, o.w};
        __half h4[4], l4[4];
#pragma unroll
        for (int k = 0; k < 4; k++) split2(v[k], h4[k], l4[k]);
        reinterpret_cast<uint2*>(Yh)[i] = *reinterpret_cast<uint2*>(h4);
        reinterpret_cast<uint2*>(Yl)[i] = *reinterpret_cast<uint2*>(l4);
    }
}

// ---------------- polar factor of 3x3 (replaces SVD U@Vh) ------------------
__global__ void polar_kernel(const float* __restrict__ O,
                             float* __restrict__ out, int B)
{
    int i = blockIdx.x * blockDim.x + threadIdx.x;
    if (i >= B * 24) return;
    int b = i / 24, j = i % 24;
    const float* m = O + (size_t)b * OUT_DIM + j * 9;
    float X[9];
#pragma unroll
    for (int k = 0; k < 9; k++) X[k] = m[k];
#pragma unroll
    for (int it = 0; it < 14; it++) {
        float C0 = X[4]*X[8] - X[5]*X[7];
        float C1 = X[5]*X[6] - X[3]*X[8];
        float C2 = X[3]*X[7] - X[4]*X[6];
        float C3 = X[2]*X[7] - X[1]*X[8];
        float C4 = X[0]*X[8] - X[2]*X[6];
        float C5 = X[1]*X[6] - X[0]*X[7];
        float C6 = X[1]*X[5] - X[2]*X[4];
        float C7 = X[2]*X[3] - X[0]*X[5];
        float C8 = X[0]*X[4] - X[1]*X[3];
        float d  = X[0]*C0 + X[1]*C1 + X[2]*C2;
        float ad = fmaxf(fabsf(d), 1e-30f);
        float g  = 1.f / cbrtf(ad);
        float c2 = copysignf(g * g, d);
        X[0] = 0.5f*(g*X[0] + c2*C0);
        X[1] = 0.5f*(g*X[1] + c2*C1);
        X[2] = 0.5f*(g*X[2] + c2*C2);
        X[3] = 0.5f*(g*X[3] + c2*C3);
        X[4] = 0.5f*(g*X[4] + c2*C4);
        X[5] = 0.5f*(g*X[5] + c2*C5);
        X[6] = 0.5f*(g*X[6] + c2*C6);
        X[7] = 0.5f*(g*X[7] + c2*C7);
        X[8] = 0.5f*(g*X[8] + c2*C8);
    }
    float det = X[0]*(X[4]*X[8]-X[5]*X[7])
              - X[1]*(X[3]*X[8]-X[5]*X[6])
              + X[2]*(X[3]*X[7]-X[4]*X[6]);
    float s = (det >= 0.f) ? 1.f : -1.f;
    float* dst = out + (size_t)i * 9;
#pragma unroll
    for (int k = 0; k < 9; k++) dst[k] = X[k] * s;
}

__global__ void tail_kernel(const float* __restrict__ O,
                            float* __restrict__ out, int B)
{
    int i = blockIdx.x * blockDim.x + threadIdx.x;
    if (i >= B * 13) return;
    int b = i / 13, t = i % 13;
    size_t betas_off  = (size_t)B * 216;
    size_t camera_off = betas_off + (size_t)B * 10;
    if (t < 10)
        out[betas_off + (size_t)b * 10 + t] = O[(size_t)b * OUT_DIM + 216 + t];
    else
        out[camera_off + (size_t)b * 3 + (t - 10)] = O[(size_t)b * OUT_DIM + 226 + (t - 10)];
}

// ---------------------------------------------------------------------------
static void launch_gemm(const __half* Ah, const __half* Al,
                        const __half* Bh, const __half* Bl,
                        const float* bias, float* C, int Kpad)
{
    dim3 grid(H_DIM / BNT, B_BATCH / BM);
    mma_gemm<<<grid, 256, SMEM_REQ>>>(Ah, Al, Bh, Bl, bias, C,
                                      Kpad, H_DIM, Kpad / BK, INV_WSCALE);
}

static void launch_bn(const float* X, const float* g, const float* be,
                      float* scale, float* shift, float* psum, float* psq,
                      const float* res, float* Yf, __half* Yh, __half* Yl)
{
    bn_stats_part<<<dim3(H_DIM / 32, BN_CH), 256>>>(X, psum, psq, B_BATCH, H_DIM);
    bn_stats_final<<<(H_DIM + 255) / 256, 256>>>(psum, psq, g, be, scale, shift,
                                                 H_DIM, B_BATCH);
    int total4 = B_BATCH * H_DIM / 4;
    bn_apply_split_kernel<<<(total4 + 255) / 256, 256>>>(X, scale, shift, res,
                                                         Yf, Yh, Yl, total4, H_DIM);
}

extern "C" void kernel_launch(void* const* d_in, const int* in_sizes, int n_in,
                              void* d_out, int out_size)
{
    const float* x    = (const float*)d_in[0];
    const float* w1   = (const float*)d_in[1];
    const float* b1   = (const float*)d_in[2];
    const float* g1   = (const float*)d_in[3];
    const float* be1  = (const float*)d_in[4];
    const float* w2a  = (const float*)d_in[5];
    const float* b2a  = (const float*)d_in[6];
    const float* g2a  = (const float*)d_in[7];
    const float* be2a = (const float*)d_in[8];
    const float* w2b  = (const float*)d_in[9];
    const float* b2b  = (const float*)d_in[10];
    const float* g2b  = (const float*)d_in[11];
    const float* be2b = (const float*)d_in[12];
    const float* w3a  = (const float*)d_in[13];
    const float* b3a  = (const float*)d_in[14];
    const float* g3a  = (const float*)d_in[15];
    const float* be3a = (const float*)d_in[16];
    const float* w3b  = (const float*)d_in[17];
    const float* b3b  = (const float*)d_in[18];
    const float* g3b  = (const float*)d_in[19];
    const float* be3b = (const float*)d_in[20];
    const float* w4   = (const float*)d_in[21];
    const float* b4   = (const float*)d_in[22];
    float* out = (float*)d_out;

    cudaFuncSetAttribute(mma_gemm, cudaFuncAttributeMaxDynamicSharedMemorySize,
                         SMEM_REQ);

    float *A, *H0, *H1, *O4, *sc, *sh, *ps, *pq;
    __half *Xh, *Xl, *AhB, *AlB;
    __half *W1h, *W1l, *W2ah, *W2al, *W2bh, *W2bl, *W3ah, *W3al, *W3bh, *W3bl;
    cudaGetSymbolAddress((void**)&A,  g_A);
    cudaGetSymbolAddress((void**)&H0, g_H0);
    cudaGetSymbolAddress((void**)&H1, g_H1);
    cudaGetSymbolAddress((void**)&O4, g_O4);
    cudaGetSymbolAddress((void**)&sc, g_scale);
    cudaGetSymbolAddress((void**)&sh, g_shift);
    cudaGetSymbolAddress((void**)&ps, g_psum);
    cudaGetSymbolAddress((void**)&pq, g_psq);
    cudaGetSymbolAddress((void**)&Xh, g_Xh);
    cudaGetSymbolAddress((void**)&Xl, g_Xl);
    cudaGetSymbolAddress((void**)&AhB, g_Ah);
    cudaGetSymbolAddress((void**)&AlB, g_Al);
    cudaGetSymbolAddress((void**)&W1h, g_W1h);   cudaGetSymbolAddress((void**)&W1l, g_W1l);
    cudaGetSymbolAddress((void**)&W2ah, g_W2ah); cudaGetSymbolAddress((void**)&W2al, g_W2al);
    cudaGetSymbolAddress((void**)&W2bh, g_W2bh); cudaGetSymbolAddress((void**)&W2bl, g_W2bl);
    cudaGetSymbolAddress((void**)&W3ah, g_W3ah); cudaGetSymbolAddress((void**)&W3al, g_W3al);
    cudaGetSymbolAddress((void**)&W3bh, g_W3bh); cudaGetSymbolAddress((void**)&W3bl, g_W3bl);

    // --- conversions -------------------------------------------------------
    {
        size_t tot = (size_t)B_BATCH * IN_PAD;
        split_pad_kernel<<<(unsigned)((tot + 255) / 256), 256>>>(x, Xh, Xl,
                                                                 B_BATCH, IN_DIM, IN_PAD);
        dim3 blk(32, 8);
        transpose_split_kernel<<<dim3(IN_PAD / 32, H_DIM / 32), blk>>>(w1, W1h, W1l, IN_DIM, H_DIM, IN_PAD);
        transpose_split_kernel<<<dim3(H_DIM / 32, H_DIM / 32), blk>>>(w2a, W2ah, W2al, H_DIM, H_DIM, H_DIM);
        transpose_split_kernel<<<dim3(H_DIM / 32, H_DIM / 32), blk>>>(w2b, W2bh, W2bl, H_DIM, H_DIM, H_DIM);
        transpose_split_kernel<<<dim3(H_DIM / 32, H_DIM / 32), blk>>>(w3a, W3ah, W3al, H_DIM, H_DIM, H_DIM);
        transpose_split_kernel<<<dim3(H_DIM / 32, H_DIM / 32), blk>>>(w3b, W3bh, W3bl, H_DIM, H_DIM, H_DIM);
    }

    // --- layer 1 -----------------------------------------------------------
    launch_gemm(Xh, Xl, W1h, W1l, b1, A, IN_PAD);
    launch_bn(A, g1, be1, sc, sh, ps, pq, nullptr, H0, AhB, AlB);

    // --- resblock 2 --------------------------------------------------------
    launch_gemm(AhB, AlB, W2ah, W2al, b2a, A, H_DIM);
    launch_bn(A, g2a, be2a, sc, sh, ps, pq, nullptr, nullptr, AhB, AlB);
    launch_gemm(AhB, AlB, W2bh, W2bl, b2b, A, H_DIM);
    launch_bn(A, g2b, be2b, sc, sh, ps, pq, H0, H1, AhB, AlB);

    // --- resblock 3 --------------------------------------------------------
    launch_gemm(AhB, AlB, W3ah, W3al, b3a, A, H_DIM);
    launch_bn(A, g3a, be3a, sc, sh, ps, pq, nullptr, nullptr, AhB, AlB);
    launch_gemm(AhB, AlB, W3bh, W3bl, b3b, A, H_DIM);
    launch_bn(A, g3b, be3b, sc, sh, ps, pq, H1, H0, nullptr, nullptr);

    // --- output head (fp32 SIMT — feeds the flip-sensitive polar stage) ----
    {
        dim3 grid((OUT_DIM + FBN - 1) / FBN, B_BATCH / FBM);
        gemm_bias_f32<<<grid, 256>>>(H0, w4, b4, O4, B_BATCH, OUT_DIM, H_DIM);
    }

    // --- polar + tail ------------------------------------------------------
    int nmat = B_BATCH * 24;
    polar_kernel<<<(nmat + 127) / 128, 128>>>(O4, out, B_BATCH);
    int ntail = B_BATCH * 13;
    tail_kernel<<<(ntail + 255) / 256, 256>>>(O4, out, B_BATCH);
}